// round 5
// baseline (speedup 1.0000x reference)
#include <cuda_runtime.h>
#include <cuda_bf16.h>
#include <math.h>

// Problem constants
#define BATCH 2
#define SEQ   2048
#define DIM   2048
#define NHEAD 16
#define HDIM  128
#define MTOT  (BATCH * SEQ)      // 4096 rows
#define ELEMS ((size_t)BATCH * SEQ * DIM)   // 8388608

// ---------------- scratch (no allocations allowed) ----------------
__device__ float g_Q[ELEMS];
__device__ float g_K[ELEMS];
__device__ float g_V[ELEMS];
__device__ float g_O[ELEMS];

// ============================================================================
// SGEMM (NT): C[m,n] = sum_k A[m,k] * B[n,k]; A:[M,K], B:[N,K], both row-major.
// 128x128 tile, BK=16, 256 threads, 8x8 per-thread micro-tile, float4 I/O.
// ============================================================================
#define BM 128
#define BN 128
#define BKK 16

__global__ __launch_bounds__(256, 2)
void sgemm_nt(const float* __restrict__ A, const float* __restrict__ B,
              float* __restrict__ C, int M, int N, int K)
{
    __shared__ float As[BKK][BM + 4];
    __shared__ float Bs[BKK][BN + 4];
    const int tid = threadIdx.x;
    const int tx = tid & 15, ty = tid >> 4;
    const int m0 = blockIdx.y * BM, n0 = blockIdx.x * BN;
    const int lr = tid >> 2;          // 0..63 (row within tile; +64 second pass)
    const int lc = (tid & 3) << 2;    // 0,4,8,12 (k offset of the float4)

    float acc[8][8];
#pragma unroll
    for (int i = 0; i < 8; i++)
#pragma unroll
        for (int j = 0; j < 8; j++) acc[i][j] = 0.f;

    for (int k0 = 0; k0 < K; k0 += BKK) {
#pragma unroll
        for (int rr = 0; rr < 2; rr++) {
            int row = lr + (rr << 6);
            float4 a = *reinterpret_cast<const float4*>(&A[(size_t)(m0 + row) * K + k0 + lc]);
            As[lc + 0][row] = a.x; As[lc + 1][row] = a.y;
            As[lc + 2][row] = a.z; As[lc + 3][row] = a.w;
            float4 bb = *reinterpret_cast<const float4*>(&B[(size_t)(n0 + row) * K + k0 + lc]);
            Bs[lc + 0][row] = bb.x; Bs[lc + 1][row] = bb.y;
            Bs[lc + 2][row] = bb.z; Bs[lc + 3][row] = bb.w;
        }
        __syncthreads();
#pragma unroll
        for (int k = 0; k < BKK; k++) {
            float4 a0 = *reinterpret_cast<const float4*>(&As[k][ty * 8]);
            float4 a1 = *reinterpret_cast<const float4*>(&As[k][ty * 8 + 4]);
            float4 b0 = *reinterpret_cast<const float4*>(&Bs[k][tx * 8]);
            float4 b1 = *reinterpret_cast<const float4*>(&Bs[k][tx * 8 + 4]);
            float av[8] = {a0.x, a0.y, a0.z, a0.w, a1.x, a1.y, a1.z, a1.w};
            float bv[8] = {b0.x, b0.y, b0.z, b0.w, b1.x, b1.y, b1.z, b1.w};
#pragma unroll
            for (int i = 0; i < 8; i++)
#pragma unroll
                for (int j = 0; j < 8; j++)
                    acc[i][j] = fmaf(av[i], bv[j], acc[i][j]);
        }
        __syncthreads();
    }

#pragma unroll
    for (int i = 0; i < 8; i++) {
        size_t crow = (size_t)(m0 + ty * 8 + i) * N + n0 + tx * 8;
        *reinterpret_cast<float4*>(&C[crow]) =
            make_float4(acc[i][0], acc[i][1], acc[i][2], acc[i][3]);
        *reinterpret_cast<float4*>(&C[crow + 4]) =
            make_float4(acc[i][4], acc[i][5], acc[i][6], acc[i][7]);
    }
}

// ============================================================================
// RoPE (non-interleaved / chunk-half), in-place on [B,S,H,D] laid out [B,S,DIM].
// angle computed via fp64 for headroom; sin/cos in accurate fp32.
// ============================================================================
__global__ __launch_bounds__(256)
void rope_kernel(float* __restrict__ buf)
{
    int idx = blockIdx.x * blockDim.x + threadIdx.x;  // [0, B*S*H*64)
    int i = idx & 63;
    int h = (idx >> 6) & (NHEAD - 1);
    int s = (idx >> 10) & (SEQ - 1);
    int b = idx >> 21;

    // inv_freq = 10000^(-(2i)/128) = exp(-i * ln(10000)/64)
    double inv = exp(-(double)i * (9.210340371976184 / 64.0));
    float ang = (float)((double)s * inv);
    float c, sn;
    sincosf(ang, &sn, &c);

    size_t base = ((size_t)b * SEQ + s) * DIM + (size_t)h * HDIM;
    float x1 = buf[base + i];
    float x2 = buf[base + 64 + i];
    buf[base + i]      = x1 * c - x2 * sn;
    buf[base + 64 + i] = x1 * sn + x2 * c;
}

// ============================================================================
// Causal flash attention, fp32. BR=BC=64, D=128, 256 threads.
// Thread (tx=tid&15, ty=tid>>4): score rows r0=ty*4, score cols c=16*j+tx
// (strided mapping -> conflict-free K-tile LDS.128), O cols oc0=tx*8.
// smem: Qs/Ks/Vs [64][132] + Ps [64][68]  = 118,784 B (dynamic).
// ============================================================================
#define FA_LDR 132   // padded row stride (floats) for Q/K/V tiles
#define FA_PSR 68    // padded row stride for P tile
#define FLASH_SMEM ((3 * 64 * FA_LDR + 64 * FA_PSR) * 4)

__global__ __launch_bounds__(256)
void flash_attn(const float* __restrict__ Q, const float* __restrict__ K,
                const float* __restrict__ V, float* __restrict__ O)
{
    const int qt = blockIdx.x;   // q tile 0..31
    const int h  = blockIdx.y;   // head
    const int b  = blockIdx.z;   // batch
    const int tid = threadIdx.x;
    const int tx = tid & 15, ty = tid >> 4;
    const int r0 = ty * 4, oc0 = tx * 8;

    extern __shared__ float sm[];
    float* Qs = sm;
    float* Ks = sm + 64 * FA_LDR;
    float* Vs = sm + 2 * 64 * FA_LDR;
    float* Ps = sm + 3 * 64 * FA_LDR;

    const size_t headoff = (size_t)h * HDIM;
    const size_t bstride = (size_t)SEQ * DIM;
    const float scale = 0.08838834764831845f;   // 1/sqrt(128)

    // Load Q tile [64][128]
    for (int t = tid; t < 64 * 32; t += 256) {
        int r = t >> 5, d = (t & 31) << 2;
        float4 v = *reinterpret_cast<const float4*>(
            &Q[(size_t)b * bstride + (size_t)(qt * 64 + r) * DIM + headoff + d]);
        *reinterpret_cast<float4*>(&Qs[r * FA_LDR + d]) = v;
    }

    float o[4][8];
#pragma unroll
    for (int i = 0; i < 4; i++)
#pragma unroll
        for (int j = 0; j < 8; j++) o[i][j] = 0.f;
    float mrow[4] = {-1e30f, -1e30f, -1e30f, -1e30f};
    float lrow[4] = {0.f, 0.f, 0.f, 0.f};

    for (int kt = 0; kt <= qt; kt++) {
        __syncthreads();   // protect Ks/Vs/Ps from previous iteration's readers
        for (int t = tid; t < 64 * 32; t += 256) {
            int r = t >> 5, d = (t & 31) << 2;
            size_t g = (size_t)b * bstride + (size_t)(kt * 64 + r) * DIM + headoff + d;
            *reinterpret_cast<float4*>(&Ks[r * FA_LDR + d]) =
                *reinterpret_cast<const float4*>(&K[g]);
            *reinterpret_cast<float4*>(&Vs[r * FA_LDR + d]) =
                *reinterpret_cast<const float4*>(&V[g]);
        }
        __syncthreads();

        // S = Q K^T   (per-thread 4x4 block; cols c = 16*j + tx)
        float s[4][4];
#pragma unroll
        for (int i = 0; i < 4; i++)
#pragma unroll
            for (int j = 0; j < 4; j++) s[i][j] = 0.f;

#pragma unroll 8
        for (int d4 = 0; d4 < 32; d4++) {
            float4 qv[4], kv[4];
#pragma unroll
            for (int i = 0; i < 4; i++)
                qv[i] = *reinterpret_cast<const float4*>(&Qs[(r0 + i) * FA_LDR + d4 * 4]);
#pragma unroll
            for (int j = 0; j < 4; j++)
                kv[j] = *reinterpret_cast<const float4*>(&Ks[(16 * j + tx) * FA_LDR + d4 * 4]);
#pragma unroll
            for (int i = 0; i < 4; i++)
#pragma unroll
                for (int j = 0; j < 4; j++)
                    s[i][j] = fmaf(qv[i].x, kv[j].x,
                              fmaf(qv[i].y, kv[j].y,
                              fmaf(qv[i].z, kv[j].z,
                              fmaf(qv[i].w, kv[j].w, s[i][j]))));
        }

        // scale + causal mask (same-size tiles: local col > local row)
#pragma unroll
        for (int i = 0; i < 4; i++)
#pragma unroll
            for (int j = 0; j < 4; j++) {
                s[i][j] *= scale;
                if (kt == qt && (16 * j + tx) > (r0 + i)) s[i][j] = -1e30f;
            }

        // online softmax per row (reduce across the 16 tx lanes)
#pragma unroll
        for (int i = 0; i < 4; i++) {
            float mt = fmaxf(fmaxf(s[i][0], s[i][1]), fmaxf(s[i][2], s[i][3]));
#pragma unroll
            for (int off = 8; off >= 1; off >>= 1)
                mt = fmaxf(mt, __shfl_xor_sync(0xffffffffu, mt, off));
            float mnew = fmaxf(mrow[i], mt);
            float alpha = __expf(mrow[i] - mnew);
            mrow[i] = mnew;
            float ls = 0.f;
#pragma unroll
            for (int j = 0; j < 4; j++) {
                s[i][j] = __expf(s[i][j] - mnew);
                ls += s[i][j];
            }
#pragma unroll
            for (int off = 8; off >= 1; off >>= 1)
                ls += __shfl_xor_sync(0xffffffffu, ls, off);
            lrow[i] = lrow[i] * alpha + ls;
#pragma unroll
            for (int j = 0; j < 8; j++) o[i][j] *= alpha;
#pragma unroll
            for (int j = 0; j < 4; j++)
                Ps[(r0 + i) * FA_PSR + 16 * j + tx] = s[i][j];
        }
        __syncthreads();

        // O += P V   (per-thread rows r0..r0+3, cols oc0..oc0+7)
#pragma unroll 4
        for (int c = 0; c < 64; c++) {
            float4 va = *reinterpret_cast<const float4*>(&Vs[c * FA_LDR + oc0]);
            float4 vb = *reinterpret_cast<const float4*>(&Vs[c * FA_LDR + oc0 + 4]);
#pragma unroll
            for (int i = 0; i < 4; i++) {
                float p = Ps[(r0 + i) * FA_PSR + c];
                o[i][0] = fmaf(p, va.x, o[i][0]);
                o[i][1] = fmaf(p, va.y, o[i][1]);
                o[i][2] = fmaf(p, va.z, o[i][2]);
                o[i][3] = fmaf(p, va.w, o[i][3]);
                o[i][4] = fmaf(p, vb.x, o[i][4]);
                o[i][5] = fmaf(p, vb.y, o[i][5]);
                o[i][6] = fmaf(p, vb.z, o[i][6]);
                o[i][7] = fmaf(p, vb.w, o[i][7]);
            }
        }
    }

    // normalize + write O[b, q, h*128 + col]
#pragma unroll
    for (int i = 0; i < 4; i++) {
        float inv = 1.f / lrow[i];
        size_t base = (size_t)b * bstride + (size_t)(qt * 64 + r0 + i) * DIM + headoff + oc0;
        *reinterpret_cast<float4*>(&O[base]) =
            make_float4(o[i][0] * inv, o[i][1] * inv, o[i][2] * inv, o[i][3] * inv);
        *reinterpret_cast<float4*>(&O[base + 4]) =
            make_float4(o[i][4] * inv, o[i][5] * inv, o[i][6] * inv, o[i][7] * inv);
    }
}

// ============================================================================
// Launch
// ============================================================================
extern "C" void kernel_launch(void* const* d_in, const int* in_sizes, int n_in,
                              void* d_out, int out_size)
{
    (void)in_sizes; (void)n_in; (void)out_size;
    const float* x  = (const float*)d_in[0];
    const float* Wq = (const float*)d_in[1];
    const float* Wk = (const float*)d_in[2];
    const float* Wv = (const float*)d_in[3];
    const float* Wo = (const float*)d_in[4];
    float* out = (float*)d_out;

    float *Qp, *Kp, *Vp, *Op;
    cudaGetSymbolAddress((void**)&Qp, g_Q);
    cudaGetSymbolAddress((void**)&Kp, g_K);
    cudaGetSymbolAddress((void**)&Vp, g_V);
    cudaGetSymbolAddress((void**)&Op, g_O);

    cudaFuncSetAttribute(flash_attn, cudaFuncAttributeMaxDynamicSharedMemorySize,
                         FLASH_SMEM);

    dim3 ggrid(DIM / BN, MTOT / BM);   // (16, 32)

    sgemm_nt<<<ggrid, 256>>>(x, Wq, Qp, MTOT, DIM, DIM);
    sgemm_nt<<<ggrid, 256>>>(x, Wk, Kp, MTOT, DIM, DIM);
    sgemm_nt<<<ggrid, 256>>>(x, Wv, Vp, MTOT, DIM, DIM);

    int rope_threads = BATCH * SEQ * NHEAD * 64;   // 4,194,304
    rope_kernel<<<rope_threads / 256, 256>>>(Qp);
    rope_kernel<<<rope_threads / 256, 256>>>(Kp);

    flash_attn<<<dim3(SEQ / 64, NHEAD, BATCH), 256, FLASH_SMEM>>>(Qp, Kp, Vp, Op);

    sgemm_nt<<<ggrid, 256>>>(Op, Wo, out, MTOT, DIM, DIM);
}

// round 7
// speedup vs baseline: 1.8202x; 1.8202x over previous
#include <cuda_runtime.h>
#include <cuda_bf16.h>
#include <math.h>
#include <stdint.h>

// Problem constants
#define BATCH 2
#define SEQ   2048
#define DIM   2048
#define NHEAD 16
#define HDIM  128
#define MTOT  (BATCH * SEQ)      // 4096 rows
#define ELEMS ((size_t)BATCH * SEQ * DIM)   // 8388608

// ---------------- scratch (no allocations allowed) ----------------
__device__ float g_Q[ELEMS];
__device__ float g_K[ELEMS];
__device__ float g_V[ELEMS];
__device__ float g_O[ELEMS];
__device__ __align__(16) __nv_bfloat16 g_ah[ELEMS];          // A hi (x or O)
__device__ __align__(16) __nv_bfloat16 g_al[ELEMS];          // A lo
__device__ __align__(16) __nv_bfloat16 g_bh[(size_t)DIM * DIM];  // W hi
__device__ __align__(16) __nv_bfloat16 g_bl[(size_t)DIM * DIM];  // W lo
__device__ double g_invfreq[64];

// ============================================================================
// mma.sync helpers (NOT arch-specific; legal at compute_103)
// ============================================================================
__device__ __forceinline__ uint32_t smem_u32(const void* p) {
    uint32_t a;
    asm("{ .reg .u64 t; cvta.to.shared.u64 t, %1; cvt.u32.u64 %0, t; }"
        : "=r"(a) : "l"(p));
    return a;
}

__device__ __forceinline__ void ldsm_x4(uint32_t (&r)[4], uint32_t addr) {
    asm volatile("ldmatrix.sync.aligned.m8n8.x4.shared.b16 {%0,%1,%2,%3}, [%4];"
                 : "=r"(r[0]), "=r"(r[1]), "=r"(r[2]), "=r"(r[3]) : "r"(addr));
}

__device__ __forceinline__ void mma_bf16(float (&c)[4], const uint32_t (&a)[4],
                                         uint32_t b0, uint32_t b1) {
    asm volatile(
        "mma.sync.aligned.m16n8k16.row.col.f32.bf16.bf16.f32 "
        "{%0,%1,%2,%3}, {%4,%5,%6,%7}, {%8,%9}, {%0,%1,%2,%3};"
        : "+f"(c[0]), "+f"(c[1]), "+f"(c[2]), "+f"(c[3])
        : "r"(a[0]), "r"(a[1]), "r"(a[2]), "r"(a[3]), "r"(b0), "r"(b1));
}

// ============================================================================
// bf16x3 tensor-core GEMM (NT): C[m,n] = sum_k A[m,k]*B[n,k]
// CTA tile 128x128, BK=32, 256 threads = 8 warps (4x2), warp tile 32x64.
// smem tiles Ah/Al/Bh/Bl: 128 rows x 32 bf16, row stride 40 bf16 (80B) ->
// ldmatrix conflict-free (80 mod 128 visits all eight 16B groups).
// ============================================================================
#define G_STRIDE 40                       // bf16 per smem row (80 bytes)
#define G_TILE_B (128 * G_STRIDE * 2)     // 10240 bytes per tile
#define TA_H 0
#define TA_L (G_TILE_B)
#define TB_H (2 * G_TILE_B)
#define TB_L (3 * G_TILE_B)

__global__ __launch_bounds__(256, 2)
void gemm_mma(const __nv_bfloat16* __restrict__ Ah, const __nv_bfloat16* __restrict__ Al,
              const __nv_bfloat16* __restrict__ Bh, const __nv_bfloat16* __restrict__ Bl,
              float* __restrict__ C, int M, int N, int K)
{
    __shared__ __align__(16) char sm[4 * G_TILE_B];   // 40960 B
    const uint32_t smb = smem_u32(sm);
    const int tid = threadIdx.x;
    const int wid = tid >> 5, lane = tid & 31;
    const int wm = wid & 3, wn = wid >> 2;            // warp grid 4x2
    const int m0 = blockIdx.y * 128, n0 = blockIdx.x * 128;

    // per-lane ldmatrix address components (bytes within a tile)
    const uint32_t aoff = (uint32_t)(((lane & 7) + 8 * ((lane >> 3) & 1)) * 80
                                     + 16 * (lane >> 4));
    const uint32_t boff = (uint32_t)(((lane & 7) + 8 * (lane >> 4)) * 80
                                     + 16 * ((lane >> 3) & 1));

    float acc[2][8][4];
#pragma unroll
    for (int i = 0; i < 2; i++)
#pragma unroll
        for (int j = 0; j < 8; j++)
#pragma unroll
            for (int v = 0; v < 4; v++) acc[i][j][v] = 0.f;

    const int KB = K >> 5;   // 64 K-blocks of 32
    for (int kb = 0; kb < KB; kb++) {
        __syncthreads();
        // load 4 tiles: each 512 x 16B chunks; 2 chunks per thread per tile
#pragma unroll
        for (int i = 0; i < 2; i++) {
            int s = tid + i * 256;            // 0..511
            int r = s >> 2, c = s & 3;        // row, 16B-chunk
            uint32_t so = (uint32_t)(r * 80 + c * 16);
            size_t ga = (size_t)(m0 + r) * K + (size_t)kb * 32 + c * 8;
            size_t gb = (size_t)(n0 + r) * K + (size_t)kb * 32 + c * 8;
            *reinterpret_cast<uint4*>(sm + TA_H + so) =
                *reinterpret_cast<const uint4*>(Ah + ga);
            *reinterpret_cast<uint4*>(sm + TA_L + so) =
                *reinterpret_cast<const uint4*>(Al + ga);
            *reinterpret_cast<uint4*>(sm + TB_H + so) =
                *reinterpret_cast<const uint4*>(Bh + gb);
            *reinterpret_cast<uint4*>(sm + TB_L + so) =
                *reinterpret_cast<const uint4*>(Bl + gb);
        }
        __syncthreads();

#pragma unroll
        for (int ks = 0; ks < 2; ks++) {
            const uint32_t kso = (uint32_t)(32 * ks);
            uint32_t ah_[2][4], al_[2][4];
#pragma unroll
            for (int f = 0; f < 2; f++) {
                uint32_t ro = (uint32_t)((wm * 32 + 16 * f) * 80);
                ldsm_x4(ah_[f], smb + TA_H + ro + aoff + kso);
                ldsm_x4(al_[f], smb + TA_L + ro + aoff + kso);
            }
            uint32_t bb[4][4];
#pragma unroll
            for (int j = 0; j < 4; j++) {
                uint32_t ro = (uint32_t)((wn * 64 + 16 * j) * 80);
                ldsm_x4(bb[j], smb + TB_H + ro + boff + kso);
            }
            // hi*hi and lo*hi
#pragma unroll
            for (int f = 0; f < 2; f++)
#pragma unroll
                for (int j = 0; j < 4; j++) {
                    mma_bf16(acc[f][2 * j + 0], ah_[f], bb[j][0], bb[j][1]);
                    mma_bf16(acc[f][2 * j + 1], ah_[f], bb[j][2], bb[j][3]);
                    mma_bf16(acc[f][2 * j + 0], al_[f], bb[j][0], bb[j][1]);
                    mma_bf16(acc[f][2 * j + 1], al_[f], bb[j][2], bb[j][3]);
                }
            // hi*lo
#pragma unroll
            for (int j = 0; j < 4; j++) {
                uint32_t ro = (uint32_t)((wn * 64 + 16 * j) * 80);
                ldsm_x4(bb[j], smb + TB_L + ro + boff + kso);
            }
#pragma unroll
            for (int f = 0; f < 2; f++)
#pragma unroll
                for (int j = 0; j < 4; j++) {
                    mma_bf16(acc[f][2 * j + 0], ah_[f], bb[j][0], bb[j][1]);
                    mma_bf16(acc[f][2 * j + 1], ah_[f], bb[j][2], bb[j][3]);
                }
        }
    }

    // epilogue
    const int g = lane >> 2, cq = lane & 3;
#pragma unroll
    for (int f = 0; f < 2; f++)
#pragma unroll
        for (int j = 0; j < 8; j++) {
            int row = m0 + wm * 32 + 16 * f + g;
            int col = n0 + wn * 64 + 8 * j + 2 * cq;
            *reinterpret_cast<float2*>(&C[(size_t)row * N + col]) =
                make_float2(acc[f][j][0], acc[f][j][1]);
            *reinterpret_cast<float2*>(&C[(size_t)(row + 8) * N + col]) =
                make_float2(acc[f][j][2], acc[f][j][3]);
        }
}

// ============================================================================
// fp32 -> bf16 hi/lo split:  hi = bf16(x), lo = bf16(x - float(hi))
// ============================================================================
__global__ __launch_bounds__(256)
void split_bf16(const float* __restrict__ in, __nv_bfloat16* __restrict__ hi,
                __nv_bfloat16* __restrict__ lo, int n4)
{
    int i = blockIdx.x * blockDim.x + threadIdx.x;
    if (i >= n4) return;
    float4 v = *reinterpret_cast<const float4*>(in + (size_t)i * 4);
    __nv_bfloat16 h0 = __float2bfloat16(v.x), h1 = __float2bfloat16(v.y);
    __nv_bfloat16 h2 = __float2bfloat16(v.z), h3 = __float2bfloat16(v.w);
    __nv_bfloat16 l0 = __float2bfloat16(v.x - __bfloat162float(h0));
    __nv_bfloat16 l1 = __float2bfloat16(v.y - __bfloat162float(h1));
    __nv_bfloat16 l2 = __float2bfloat16(v.z - __bfloat162float(h2));
    __nv_bfloat16 l3 = __float2bfloat16(v.w - __bfloat162float(h3));
    __nv_bfloat162* H = reinterpret_cast<__nv_bfloat162*>(hi) + (size_t)i * 2;
    __nv_bfloat162* L = reinterpret_cast<__nv_bfloat162*>(lo) + (size_t)i * 2;
    H[0] = __nv_bfloat162(h0, h1); H[1] = __nv_bfloat162(h2, h3);
    L[0] = __nv_bfloat162(l0, l1); L[1] = __nv_bfloat162(l2, l3);
}

// ============================================================================
// RoPE: inv_freq table precomputed in fp64 (once); rope does DMUL + sincosf.
// ============================================================================
__global__ void init_invfreq()
{
    int i = threadIdx.x;
    g_invfreq[i] = exp(-(double)i * (9.210340371976184 / 64.0));
}

__global__ __launch_bounds__(256)
void rope_kernel(float* __restrict__ buf)
{
    int idx = blockIdx.x * blockDim.x + threadIdx.x;  // [0, B*S*H*64)
    int i = idx & 63;
    int h = (idx >> 6) & (NHEAD - 1);
    int s = (idx >> 10) & (SEQ - 1);
    int b = idx >> 21;

    double inv = g_invfreq[i];
    float ang = (float)((double)s * inv);
    float c, sn;
    sincosf(ang, &sn, &c);

    size_t base = ((size_t)b * SEQ + s) * DIM + (size_t)h * HDIM;
    float x1 = buf[base + i];
    float x2 = buf[base + 64 + i];
    buf[base + i]      = x1 * c - x2 * sn;
    buf[base + 64 + i] = x1 * sn + x2 * c;
}

// ============================================================================
// Causal flash attention, fp32. BR=BC=64, D=128, 256 threads. (unchanged)
// ============================================================================
#define FA_LDR 132
#define FA_PSR 68
#define FLASH_SMEM ((3 * 64 * FA_LDR + 64 * FA_PSR) * 4)

__global__ __launch_bounds__(256)
void flash_attn(const float* __restrict__ Q, const float* __restrict__ K,
                const float* __restrict__ V, float* __restrict__ O)
{
    const int qt = blockIdx.x;
    const int h  = blockIdx.y;
    const int b  = blockIdx.z;
    const int tid = threadIdx.x;
    const int tx = tid & 15, ty = tid >> 4;
    const int r0 = ty * 4, oc0 = tx * 8;

    extern __shared__ float smf[];
    float* Qs = smf;
    float* Ks = smf + 64 * FA_LDR;
    float* Vs = smf + 2 * 64 * FA_LDR;
    float* Ps = smf + 3 * 64 * FA_LDR;

    const size_t headoff = (size_t)h * HDIM;
    const size_t bstride = (size_t)SEQ * DIM;
    const float scale = 0.08838834764831845f;

    for (int t = tid; t < 64 * 32; t += 256) {
        int r = t >> 5, d = (t & 31) << 2;
        float4 v = *reinterpret_cast<const float4*>(
            &Q[(size_t)b * bstride + (size_t)(qt * 64 + r) * DIM + headoff + d]);
        *reinterpret_cast<float4*>(&Qs[r * FA_LDR + d]) = v;
    }

    float o[4][8];
#pragma unroll
    for (int i = 0; i < 4; i++)
#pragma unroll
        for (int j = 0; j < 8; j++) o[i][j] = 0.f;
    float mrow[4] = {-1e30f, -1e30f, -1e30f, -1e30f};
    float lrow[4] = {0.f, 0.f, 0.f, 0.f};

    for (int kt = 0; kt <= qt; kt++) {
        __syncthreads();
        for (int t = tid; t < 64 * 32; t += 256) {
            int r = t >> 5, d = (t & 31) << 2;
            size_t g = (size_t)b * bstride + (size_t)(kt * 64 + r) * DIM + headoff + d;
            *reinterpret_cast<float4*>(&Ks[r * FA_LDR + d]) =
                *reinterpret_cast<const float4*>(&K[g]);
            *reinterpret_cast<float4*>(&Vs[r * FA_LDR + d]) =
                *reinterpret_cast<const float4*>(&V[g]);
        }
        __syncthreads();

        float s[4][4];
#pragma unroll
        for (int i = 0; i < 4; i++)
#pragma unroll
            for (int j = 0; j < 4; j++) s[i][j] = 0.f;

#pragma unroll 8
        for (int d4 = 0; d4 < 32; d4++) {
            float4 qv[4], kv[4];
#pragma unroll
            for (int i = 0; i < 4; i++)
                qv[i] = *reinterpret_cast<const float4*>(&Qs[(r0 + i) * FA_LDR + d4 * 4]);
#pragma unroll
            for (int j = 0; j < 4; j++)
                kv[j] = *reinterpret_cast<const float4*>(&Ks[(16 * j + tx) * FA_LDR + d4 * 4]);
#pragma unroll
            for (int i = 0; i < 4; i++)
#pragma unroll
                for (int j = 0; j < 4; j++)
                    s[i][j] = fmaf(qv[i].x, kv[j].x,
                              fmaf(qv[i].y, kv[j].y,
                              fmaf(qv[i].z, kv[j].z,
                              fmaf(qv[i].w, kv[j].w, s[i][j]))));
        }

#pragma unroll
        for (int i = 0; i < 4; i++)
#pragma unroll
            for (int j = 0; j < 4; j++) {
                s[i][j] *= scale;
                if (kt == qt && (16 * j + tx) > (r0 + i)) s[i][j] = -1e30f;
            }

#pragma unroll
        for (int i = 0; i < 4; i++) {
            float mt = fmaxf(fmaxf(s[i][0], s[i][1]), fmaxf(s[i][2], s[i][3]));
#pragma unroll
            for (int off = 8; off >= 1; off >>= 1)
                mt = fmaxf(mt, __shfl_xor_sync(0xffffffffu, mt, off));
            float mnew = fmaxf(mrow[i], mt);
            float alpha = __expf(mrow[i] - mnew);
            mrow[i] = mnew;
            float ls = 0.f;
#pragma unroll
            for (int j = 0; j < 4; j++) {
                s[i][j] = __expf(s[i][j] - mnew);
                ls += s[i][j];
            }
#pragma unroll
            for (int off = 8; off >= 1; off >>= 1)
                ls += __shfl_xor_sync(0xffffffffu, ls, off);
            lrow[i] = lrow[i] * alpha + ls;
#pragma unroll
            for (int j = 0; j < 8; j++) o[i][j] *= alpha;
#pragma unroll
            for (int j = 0; j < 4; j++)
                Ps[(r0 + i) * FA_PSR + 16 * j + tx] = s[i][j];
        }
        __syncthreads();

#pragma unroll 4
        for (int c = 0; c < 64; c++) {
            float4 va = *reinterpret_cast<const float4*>(&Vs[c * FA_LDR + oc0]);
            float4 vb = *reinterpret_cast<const float4*>(&Vs[c * FA_LDR + oc0 + 4]);
#pragma unroll
            for (int i = 0; i < 4; i++) {
                float p = Ps[(r0 + i) * FA_PSR + c];
                o[i][0] = fmaf(p, va.x, o[i][0]);
                o[i][1] = fmaf(p, va.y, o[i][1]);
                o[i][2] = fmaf(p, va.z, o[i][2]);
                o[i][3] = fmaf(p, va.w, o[i][3]);
                o[i][4] = fmaf(p, vb.x, o[i][4]);
                o[i][5] = fmaf(p, vb.y, o[i][5]);
                o[i][6] = fmaf(p, vb.z, o[i][6]);
                o[i][7] = fmaf(p, vb.w, o[i][7]);
            }
        }
    }

#pragma unroll
    for (int i = 0; i < 4; i++) {
        float inv = 1.f / lrow[i];
        size_t base = (size_t)b * bstride + (size_t)(qt * 64 + r0 + i) * DIM + headoff + oc0;
        *reinterpret_cast<float4*>(&O[base]) =
            make_float4(o[i][0] * inv, o[i][1] * inv, o[i][2] * inv, o[i][3] * inv);
        *reinterpret_cast<float4*>(&O[base + 4]) =
            make_float4(o[i][4] * inv, o[i][5] * inv, o[i][6] * inv, o[i][7] * inv);
    }
}

// ============================================================================
// Launch
// ============================================================================
extern "C" void kernel_launch(void* const* d_in, const int* in_sizes, int n_in,
                              void* d_out, int out_size)
{
    (void)in_sizes; (void)n_in; (void)out_size;
    const float* x  = (const float*)d_in[0];
    const float* Wq = (const float*)d_in[1];
    const float* Wk = (const float*)d_in[2];
    const float* Wv = (const float*)d_in[3];
    const float* Wo = (const float*)d_in[4];
    float* out = (float*)d_out;

    float *Qp, *Kp, *Vp, *Op;
    __nv_bfloat16 *ah, *al, *bh, *bl;
    cudaGetSymbolAddress((void**)&Qp, g_Q);
    cudaGetSymbolAddress((void**)&Kp, g_K);
    cudaGetSymbolAddress((void**)&Vp, g_V);
    cudaGetSymbolAddress((void**)&Op, g_O);
    cudaGetSymbolAddress((void**)&ah, g_ah);
    cudaGetSymbolAddress((void**)&al, g_al);
    cudaGetSymbolAddress((void**)&bh, g_bh);
    cudaGetSymbolAddress((void**)&bl, g_bl);

    cudaFuncSetAttribute(flash_attn, cudaFuncAttributeMaxDynamicSharedMemorySize,
                         FLASH_SMEM);

    const dim3 ggrid(DIM / 128, MTOT / 128);   // (16, 32)
    const int nx4 = (int)(ELEMS / 4);
    const int nw4 = (int)(((size_t)DIM * DIM) / 4);

    init_invfreq<<<1, 64>>>();

    // QKV projections
    split_bf16<<<(nx4 + 255) / 256, 256>>>(x, ah, al, nx4);
    split_bf16<<<(nw4 + 255) / 256, 256>>>(Wq, bh, bl, nw4);
    gemm_mma<<<ggrid, 256>>>(ah, al, bh, bl, Qp, MTOT, DIM, DIM);
    split_bf16<<<(nw4 + 255) / 256, 256>>>(Wk, bh, bl, nw4);
    gemm_mma<<<ggrid, 256>>>(ah, al, bh, bl, Kp, MTOT, DIM, DIM);
    split_bf16<<<(nw4 + 255) / 256, 256>>>(Wv, bh, bl, nw4);
    gemm_mma<<<ggrid, 256>>>(ah, al, bh, bl, Vp, MTOT, DIM, DIM);

    // RoPE
    int rope_threads = BATCH * SEQ * NHEAD * 64;
    rope_kernel<<<rope_threads / 256, 256>>>(Qp);
    rope_kernel<<<rope_threads / 256, 256>>>(Kp);

    // Attention
    flash_attn<<<dim3(SEQ / 64, NHEAD, BATCH), 256, FLASH_SMEM>>>(Qp, Kp, Vp, Op);

    // Output projection
    split_bf16<<<(nx4 + 255) / 256, 256>>>(Op, ah, al, nx4);
    split_bf16<<<(nw4 + 255) / 256, 256>>>(Wo, bh, bl, nw4);
    gemm_mma<<<ggrid, 256>>>(ah, al, bh, bl, out, MTOT, DIM, DIM);
}

// round 8
// speedup vs baseline: 2.9775x; 1.6358x over previous
#include <cuda_runtime.h>
#include <cuda_bf16.h>
#include <math.h>
#include <stdint.h>

// Problem constants
#define BATCH 2
#define SEQ   2048
#define DIM   2048
#define NHEAD 16
#define HDIM  128
#define MTOT  (BATCH * SEQ)      // 4096 rows
#define ELEMS ((size_t)BATCH * SEQ * DIM)   // 8388608

// ---------------- scratch (no allocations allowed) ----------------
__device__ float g_Q[ELEMS];
__device__ float g_K[ELEMS];
__device__ float g_V[ELEMS];
__device__ float g_O[ELEMS];
__device__ __align__(16) __nv_bfloat16 g_ah[ELEMS];              // A hi (x or O)
__device__ __align__(16) __nv_bfloat16 g_al[ELEMS];              // A lo
__device__ __align__(16) __nv_bfloat16 g_bh[(size_t)DIM * DIM];  // W hi
__device__ __align__(16) __nv_bfloat16 g_bl[(size_t)DIM * DIM];  // W lo
__device__ __align__(16) __nv_bfloat16 g_qh[ELEMS];
__device__ __align__(16) __nv_bfloat16 g_ql[ELEMS];
__device__ __align__(16) __nv_bfloat16 g_kh[ELEMS];
__device__ __align__(16) __nv_bfloat16 g_kl[ELEMS];
__device__ __align__(16) __nv_bfloat16 g_vh[ELEMS];
__device__ __align__(16) __nv_bfloat16 g_vl[ELEMS];
__device__ double g_invfreq[64];

// ============================================================================
// mma.sync / ldmatrix / cp.async helpers (all legal at compute_103)
// ============================================================================
__device__ __forceinline__ uint32_t smem_u32(const void* p) {
    uint32_t a;
    asm("{ .reg .u64 t; cvta.to.shared.u64 t, %1; cvt.u32.u64 %0, t; }"
        : "=r"(a) : "l"(p));
    return a;
}

__device__ __forceinline__ void ldsm_x4(uint32_t (&r)[4], uint32_t addr) {
    asm volatile("ldmatrix.sync.aligned.m8n8.x4.shared.b16 {%0,%1,%2,%3}, [%4];"
                 : "=r"(r[0]), "=r"(r[1]), "=r"(r[2]), "=r"(r[3]) : "r"(addr));
}

__device__ __forceinline__ void ldsm_x4_t(uint32_t (&r)[4], uint32_t addr) {
    asm volatile("ldmatrix.sync.aligned.m8n8.x4.trans.shared.b16 {%0,%1,%2,%3}, [%4];"
                 : "=r"(r[0]), "=r"(r[1]), "=r"(r[2]), "=r"(r[3]) : "r"(addr));
}

__device__ __forceinline__ void mma_bf16(float (&c)[4], const uint32_t (&a)[4],
                                         uint32_t b0, uint32_t b1) {
    asm volatile(
        "mma.sync.aligned.m16n8k16.row.col.f32.bf16.bf16.f32 "
        "{%0,%1,%2,%3}, {%4,%5,%6,%7}, {%8,%9}, {%0,%1,%2,%3};"
        : "+f"(c[0]), "+f"(c[1]), "+f"(c[2]), "+f"(c[3])
        : "r"(a[0]), "r"(a[1]), "r"(a[2]), "r"(a[3]), "r"(b0), "r"(b1));
}

#define CP_ASYNC16(dst, src) \
    asm volatile("cp.async.ca.shared.global [%0], [%1], 16;" \
                 :: "r"(dst), "l"(src) : "memory")
#define CP_COMMIT() asm volatile("cp.async.commit_group;" ::: "memory")
#define CP_WAIT0()  asm volatile("cp.async.wait_group 0;" ::: "memory")

// ============================================================================
// bf16x3 tensor-core GEMM (NT): C[m,n] = sum_k A[m,k]*B[n,k]
// CTA tile 128x128, BK=32, 256 threads = 8 warps (4x2), warp tile 32x64.
// Double-buffered via cp.async. smem row stride 40 bf16 (80B, conflict-free).
// ============================================================================
#define G_STRIDE 40
#define G_TILE_B (128 * G_STRIDE * 2)     // 10240 bytes per tile
#define G_STAGE  (4 * G_TILE_B)           // 40960 per stage
#define TA_H 0
#define TA_L (G_TILE_B)
#define TB_H (2 * G_TILE_B)
#define TB_L (3 * G_TILE_B)
#define G_SMEM (2 * G_STAGE)              // 81920

__global__ __launch_bounds__(256, 2)
void gemm_mma(const __nv_bfloat16* __restrict__ Ah, const __nv_bfloat16* __restrict__ Al,
              const __nv_bfloat16* __restrict__ Bh, const __nv_bfloat16* __restrict__ Bl,
              float* __restrict__ C, int M, int N, int K)
{
    extern __shared__ __align__(16) char sm[];
    const uint32_t smb = smem_u32(sm);
    const int tid = threadIdx.x;
    const int wid = tid >> 5, lane = tid & 31;
    const int wm = wid & 3, wn = wid >> 2;
    const int m0 = blockIdx.y * 128, n0 = blockIdx.x * 128;

    const uint32_t aoff = (uint32_t)(((lane & 7) + 8 * ((lane >> 3) & 1)) * 80
                                     + 16 * (lane >> 4));
    const uint32_t boff = (uint32_t)(((lane & 7) + 8 * (lane >> 4)) * 80
                                     + 16 * ((lane >> 3) & 1));

    // per-thread load coords (2 chunks per tile)
    const int lr0 = tid >> 2, lc0 = (tid & 3);           // chunk 0: rows 0..63
    const int lr1 = lr0 + 64, lc1 = lc0;                 // chunk 1: rows 64..127

    auto load_tiles = [&](int kb, int st) {
        uint32_t base = smb + (uint32_t)(st * G_STAGE);
        uint32_t so0 = (uint32_t)(lr0 * 80 + lc0 * 16);
        uint32_t so1 = (uint32_t)(lr1 * 80 + lc1 * 16);
        size_t ga0 = (size_t)(m0 + lr0) * K + (size_t)kb * 32 + lc0 * 8;
        size_t ga1 = (size_t)(m0 + lr1) * K + (size_t)kb * 32 + lc1 * 8;
        size_t gb0 = (size_t)(n0 + lr0) * K + (size_t)kb * 32 + lc0 * 8;
        size_t gb1 = (size_t)(n0 + lr1) * K + (size_t)kb * 32 + lc1 * 8;
        CP_ASYNC16(base + TA_H + so0, Ah + ga0);
        CP_ASYNC16(base + TA_H + so1, Ah + ga1);
        CP_ASYNC16(base + TA_L + so0, Al + ga0);
        CP_ASYNC16(base + TA_L + so1, Al + ga1);
        CP_ASYNC16(base + TB_H + so0, Bh + gb0);
        CP_ASYNC16(base + TB_H + so1, Bh + gb1);
        CP_ASYNC16(base + TB_L + so0, Bl + gb0);
        CP_ASYNC16(base + TB_L + so1, Bl + gb1);
        CP_COMMIT();
    };

    float acc[2][8][4];
#pragma unroll
    for (int i = 0; i < 2; i++)
#pragma unroll
        for (int j = 0; j < 8; j++)
#pragma unroll
            for (int v = 0; v < 4; v++) acc[i][j][v] = 0.f;

    const int KB = K >> 5;
    load_tiles(0, 0);
    int st = 0;
    for (int kb = 0; kb < KB; kb++) {
        CP_WAIT0();
        __syncthreads();
        if (kb + 1 < KB) load_tiles(kb + 1, st ^ 1);

        const uint32_t sb = smb + (uint32_t)(st * G_STAGE);
#pragma unroll
        for (int ks = 0; ks < 2; ks++) {
            const uint32_t kso = (uint32_t)(32 * ks);
            uint32_t ah_[2][4], al_[2][4];
#pragma unroll
            for (int f = 0; f < 2; f++) {
                uint32_t ro = (uint32_t)((wm * 32 + 16 * f) * 80);
                ldsm_x4(ah_[f], sb + TA_H + ro + aoff + kso);
                ldsm_x4(al_[f], sb + TA_L + ro + aoff + kso);
            }
            uint32_t bb[4][4];
#pragma unroll
            for (int j = 0; j < 4; j++) {
                uint32_t ro = (uint32_t)((wn * 64 + 16 * j) * 80);
                ldsm_x4(bb[j], sb + TB_H + ro + boff + kso);
            }
#pragma unroll
            for (int f = 0; f < 2; f++)
#pragma unroll
                for (int j = 0; j < 4; j++) {
                    mma_bf16(acc[f][2 * j + 0], ah_[f], bb[j][0], bb[j][1]);
                    mma_bf16(acc[f][2 * j + 1], ah_[f], bb[j][2], bb[j][3]);
                    mma_bf16(acc[f][2 * j + 0], al_[f], bb[j][0], bb[j][1]);
                    mma_bf16(acc[f][2 * j + 1], al_[f], bb[j][2], bb[j][3]);
                }
#pragma unroll
            for (int j = 0; j < 4; j++) {
                uint32_t ro = (uint32_t)((wn * 64 + 16 * j) * 80);
                ldsm_x4(bb[j], sb + TB_L + ro + boff + kso);
            }
#pragma unroll
            for (int f = 0; f < 2; f++)
#pragma unroll
                for (int j = 0; j < 4; j++) {
                    mma_bf16(acc[f][2 * j + 0], ah_[f], bb[j][0], bb[j][1]);
                    mma_bf16(acc[f][2 * j + 1], ah_[f], bb[j][2], bb[j][3]);
                }
        }
        st ^= 1;
    }

    const int g = lane >> 2, cq = lane & 3;
#pragma unroll
    for (int f = 0; f < 2; f++)
#pragma unroll
        for (int j = 0; j < 8; j++) {
            int row = m0 + wm * 32 + 16 * f + g;
            int col = n0 + wn * 64 + 8 * j + 2 * cq;
            *reinterpret_cast<float2*>(&C[(size_t)row * N + col]) =
                make_float2(acc[f][j][0], acc[f][j][1]);
            *reinterpret_cast<float2*>(&C[(size_t)(row + 8) * N + col]) =
                make_float2(acc[f][j][2], acc[f][j][3]);
        }
}

// ============================================================================
// fp32 -> bf16 hi/lo split
// ============================================================================
__global__ __launch_bounds__(256)
void split_bf16(const float* __restrict__ in, __nv_bfloat16* __restrict__ hi,
                __nv_bfloat16* __restrict__ lo, int n4)
{
    int i = blockIdx.x * blockDim.x + threadIdx.x;
    if (i >= n4) return;
    float4 v = *reinterpret_cast<const float4*>(in + (size_t)i * 4);
    __nv_bfloat16 h0 = __float2bfloat16(v.x), h1 = __float2bfloat16(v.y);
    __nv_bfloat16 h2 = __float2bfloat16(v.z), h3 = __float2bfloat16(v.w);
    __nv_bfloat16 l0 = __float2bfloat16(v.x - __bfloat162float(h0));
    __nv_bfloat16 l1 = __float2bfloat16(v.y - __bfloat162float(h1));
    __nv_bfloat16 l2 = __float2bfloat16(v.z - __bfloat162float(h2));
    __nv_bfloat16 l3 = __float2bfloat16(v.w - __bfloat162float(h3));
    __nv_bfloat162* H = reinterpret_cast<__nv_bfloat162*>(hi) + (size_t)i * 2;
    __nv_bfloat162* L = reinterpret_cast<__nv_bfloat162*>(lo) + (size_t)i * 2;
    H[0] = __nv_bfloat162(h0, h1); H[1] = __nv_bfloat162(h2, h3);
    L[0] = __nv_bfloat162(l0, l1); L[1] = __nv_bfloat162(l2, l3);
}

// ============================================================================
// RoPE fused with bf16 hi/lo split (reads fp32, writes hi/lo bf16)
// ============================================================================
__global__ void init_invfreq()
{
    int i = threadIdx.x;
    g_invfreq[i] = exp(-(double)i * (9.210340371976184 / 64.0));
}

__global__ __launch_bounds__(256)
void rope_split(const float* __restrict__ in, __nv_bfloat16* __restrict__ hi,
                __nv_bfloat16* __restrict__ lo)
{
    int idx = blockIdx.x * blockDim.x + threadIdx.x;  // [0, B*S*H*64)
    int i = idx & 63;
    int h = (idx >> 6) & (NHEAD - 1);
    int s = (idx >> 10) & (SEQ - 1);
    int b = idx >> 21;

    double inv = g_invfreq[i];
    float ang = (float)((double)s * inv);
    float c, sn;
    sincosf(ang, &sn, &c);

    size_t base = ((size_t)b * SEQ + s) * DIM + (size_t)h * HDIM;
    float x1 = in[base + i];
    float x2 = in[base + 64 + i];
    float y1 = x1 * c - x2 * sn;
    float y2 = x1 * sn + x2 * c;

    __nv_bfloat16 h1 = __float2bfloat16(y1);
    __nv_bfloat16 h2 = __float2bfloat16(y2);
    hi[base + i]      = h1;
    hi[base + 64 + i] = h2;
    lo[base + i]      = __float2bfloat16(y1 - __bfloat162float(h1));
    lo[base + 64 + i] = __float2bfloat16(y2 - __bfloat162float(h2));
}

// ============================================================================
// Tensor-core causal flash attention, bf16x3 split, fp32 softmax/accum.
// CTA: 128 q-rows x 1 head x 1 batch. 256 threads = 8 warps x 16 rows.
// K-tile BC=64. smem strides: Q/K/V 136 bf16 (272B), P 72 bf16 (144B).
// ============================================================================
#define FQ_STR 272            // bytes per Q/K/V smem row
#define FP_STR 144            // bytes per P smem row
#define FQ_H 0
#define FQ_L (FQ_H + 128 * FQ_STR)     // 34816
#define FK_H (FQ_L + 128 * FQ_STR)     // 69632
#define FK_L (FK_H + 64 * FQ_STR)      // 87040
#define FV_H (FK_L + 64 * FQ_STR)      // 104448
#define FV_L (FV_H + 64 * FQ_STR)      // 121856
#define FP_H (FV_L + 64 * FQ_STR)      // 139264
#define FP_L (FP_H + 128 * FP_STR)     // 157696
#define F_SMEM (FP_L + 128 * FP_STR)   // 176128

__global__ __launch_bounds__(256, 1)
void flash_mma(const __nv_bfloat16* __restrict__ Qh, const __nv_bfloat16* __restrict__ Ql,
               const __nv_bfloat16* __restrict__ Kh, const __nv_bfloat16* __restrict__ Kl,
               const __nv_bfloat16* __restrict__ Vh, const __nv_bfloat16* __restrict__ Vl,
               float* __restrict__ O)
{
    extern __shared__ __align__(16) char sm[];
    const uint32_t smb = smem_u32(sm);
    const int qt = (int)gridDim.x - 1 - (int)blockIdx.x;  // big tiles first
    const int h  = blockIdx.y;
    const int b  = blockIdx.z;
    const int tid = threadIdx.x;
    const int wid = tid >> 5, lane = tid & 31;
    const int g = lane >> 2, cq = lane & 3;
    const float scale = 0.08838834764831845f;   // 1/sqrt(128)

    // ldmatrix lane-address components
    const uint32_t aoffQ = (uint32_t)((lane & 15) * FQ_STR + 16 * (lane >> 4));
    const uint32_t boffK = (uint32_t)(((lane & 7) + 8 * (lane >> 4)) * FQ_STR
                                      + 16 * ((lane >> 3) & 1));
    const uint32_t aoffP = (uint32_t)((lane & 15) * FP_STR + 16 * (lane >> 4));
    const uint32_t toffV = (uint32_t)(((lane & 7) + 8 * ((lane >> 3) & 1)) * FQ_STR
                                      + 16 * (lane >> 4));

    const size_t rowbase = (size_t)b * SEQ;     // gmem row index base
    const size_t coloff = (size_t)h * HDIM;

    // ---- load Q tile (128 x 128 bf16, hi+lo) ----
#pragma unroll
    for (int i = 0; i < 8; i++) {
        int s = tid + i * 256;                  // 0..2047
        int r = s >> 4, c = s & 15;
        uint32_t so = (uint32_t)(r * FQ_STR + c * 16);
        size_t ga = (rowbase + qt * 128 + r) * DIM + coloff + c * 8;
        *reinterpret_cast<uint4*>(sm + FQ_H + so) =
            *reinterpret_cast<const uint4*>(Qh + ga);
        *reinterpret_cast<uint4*>(sm + FQ_L + so) =
            *reinterpret_cast<const uint4*>(Ql + ga);
    }

    float oacc[16][4];
#pragma unroll
    for (int f = 0; f < 16; f++)
#pragma unroll
        for (int v = 0; v < 4; v++) oacc[f][v] = 0.f;
    float m0 = -1e30f, m1 = -1e30f, l0 = 0.f, l1 = 0.f;

    const int KT = 2 * qt + 2;
    for (int kt = 0; kt < KT; kt++) {
        __syncthreads();   // K/V/P smem safe to overwrite
        // ---- load K,V tiles (64 x 128, hi+lo each) ----
#pragma unroll
        for (int i = 0; i < 4; i++) {
            int s = tid + i * 256;              // 0..1023
            int r = s >> 4, c = s & 15;
            uint32_t so = (uint32_t)(r * FQ_STR + c * 16);
            size_t ga = (rowbase + kt * 64 + r) * DIM + coloff + c * 8;
            *reinterpret_cast<uint4*>(sm + FK_H + so) =
                *reinterpret_cast<const uint4*>(Kh + ga);
            *reinterpret_cast<uint4*>(sm + FK_L + so) =
                *reinterpret_cast<const uint4*>(Kl + ga);
            *reinterpret_cast<uint4*>(sm + FV_H + so) =
                *reinterpret_cast<const uint4*>(Vh + ga);
            *reinterpret_cast<uint4*>(sm + FV_L + so) =
                *reinterpret_cast<const uint4*>(Vl + ga);
        }
        __syncthreads();

        // ---- S = Q K^T (bf16x3) ----
        float sacc[8][4];
#pragma unroll
        for (int j = 0; j < 8; j++)
#pragma unroll
            for (int v = 0; v < 4; v++) sacc[j][v] = 0.f;

        const uint32_t qrow = (uint32_t)(wid * 16 * FQ_STR);
#pragma unroll
        for (int ks = 0; ks < 8; ks++) {
            const uint32_t kso = (uint32_t)(32 * ks);
            uint32_t ah_[4], al_[4], bh_[4], bl_[4];
            ldsm_x4(ah_, smb + FQ_H + qrow + aoffQ + kso);
            ldsm_x4(al_, smb + FQ_L + qrow + aoffQ + kso);
#pragma unroll
            for (int J = 0; J < 4; J++) {
                uint32_t ro = (uint32_t)(J * 16 * FQ_STR);
                ldsm_x4(bh_, smb + FK_H + ro + boffK + kso);
                mma_bf16(sacc[2 * J + 0], ah_, bh_[0], bh_[1]);
                mma_bf16(sacc[2 * J + 1], ah_, bh_[2], bh_[3]);
                mma_bf16(sacc[2 * J + 0], al_, bh_[0], bh_[1]);
                mma_bf16(sacc[2 * J + 1], al_, bh_[2], bh_[3]);
                ldsm_x4(bl_, smb + FK_L + ro + boffK + kso);
                mma_bf16(sacc[2 * J + 0], ah_, bl_[0], bl_[1]);
                mma_bf16(sacc[2 * J + 1], ah_, bl_[2], bl_[3]);
            }
        }

        // ---- scale + causal mask ----
        const int row0 = qt * 128 + wid * 16 + g;
        const int row1 = row0 + 8;
        const bool diag = (kt >= 2 * qt);
#pragma unroll
        for (int j = 0; j < 8; j++) {
            int colb = kt * 64 + 8 * j + 2 * cq;
#pragma unroll
            for (int v = 0; v < 4; v++) sacc[j][v] *= scale;
            if (diag) {
                if (colb     > row0) sacc[j][0] = -1e30f;
                if (colb + 1 > row0) sacc[j][1] = -1e30f;
                if (colb     > row1) sacc[j][2] = -1e30f;
                if (colb + 1 > row1) sacc[j][3] = -1e30f;
            }
        }

        // ---- online softmax (rows row0, row1) ----
        float mt0 = -1e30f, mt1 = -1e30f;
#pragma unroll
        for (int j = 0; j < 8; j++) {
            mt0 = fmaxf(mt0, fmaxf(sacc[j][0], sacc[j][1]));
            mt1 = fmaxf(mt1, fmaxf(sacc[j][2], sacc[j][3]));
        }
        mt0 = fmaxf(mt0, __shfl_xor_sync(0xffffffffu, mt0, 1));
        mt0 = fmaxf(mt0, __shfl_xor_sync(0xffffffffu, mt0, 2));
        mt1 = fmaxf(mt1, __shfl_xor_sync(0xffffffffu, mt1, 1));
        mt1 = fmaxf(mt1, __shfl_xor_sync(0xffffffffu, mt1, 2));

        float mn0 = fmaxf(m0, mt0), mn1 = fmaxf(m1, mt1);
        float a0 = __expf(m0 - mn0), a1 = __expf(m1 - mn1);
        m0 = mn0; m1 = mn1;

        float ls0 = 0.f, ls1 = 0.f;
        const uint32_t prow0 = (uint32_t)((wid * 16 + g) * FP_STR);
        const uint32_t prow1 = prow0 + (uint32_t)(8 * FP_STR);
#pragma unroll
        for (int j = 0; j < 8; j++) {
            float p0 = __expf(sacc[j][0] - mn0);
            float p1 = __expf(sacc[j][1] - mn0);
            float p2 = __expf(sacc[j][2] - mn1);
            float p3 = __expf(sacc[j][3] - mn1);
            ls0 += p0 + p1; ls1 += p2 + p3;
            __nv_bfloat16 h01a = __float2bfloat16(p0), h01b = __float2bfloat16(p1);
            __nv_bfloat16 h23a = __float2bfloat16(p2), h23b = __float2bfloat16(p3);
            __nv_bfloat16 l01a = __float2bfloat16(p0 - __bfloat162float(h01a));
            __nv_bfloat16 l01b = __float2bfloat16(p1 - __bfloat162float(h01b));
            __nv_bfloat16 l23a = __float2bfloat16(p2 - __bfloat162float(h23a));
            __nv_bfloat16 l23b = __float2bfloat16(p3 - __bfloat162float(h23b));
            uint32_t cb = (uint32_t)((8 * j + 2 * cq) * 2);
            *reinterpret_cast<__nv_bfloat162*>(sm + FP_H + prow0 + cb) =
                __nv_bfloat162(h01a, h01b);
            *reinterpret_cast<__nv_bfloat162*>(sm + FP_H + prow1 + cb) =
                __nv_bfloat162(h23a, h23b);
            *reinterpret_cast<__nv_bfloat162*>(sm + FP_L + prow0 + cb) =
                __nv_bfloat162(l01a, l01b);
            *reinterpret_cast<__nv_bfloat162*>(sm + FP_L + prow1 + cb) =
                __nv_bfloat162(l23a, l23b);
        }
        ls0 += __shfl_xor_sync(0xffffffffu, ls0, 1);
        ls0 += __shfl_xor_sync(0xffffffffu, ls0, 2);
        ls1 += __shfl_xor_sync(0xffffffffu, ls1, 1);
        ls1 += __shfl_xor_sync(0xffffffffu, ls1, 2);
        l0 = l0 * a0 + ls0;
        l1 = l1 * a1 + ls1;
#pragma unroll
        for (int f = 0; f < 16; f++) {
            oacc[f][0] *= a0; oacc[f][1] *= a0;
            oacc[f][2] *= a1; oacc[f][3] *= a1;
        }
        __syncwarp();   // P stores visible to this warp's ldmatrix

        // ---- O += P V (bf16x3) ----
        const uint32_t pw = (uint32_t)(wid * 16 * FP_STR);
#pragma unroll
        for (int ks = 0; ks < 4; ks++) {
            uint32_t ph_[4], pl_[4], vh_[4], vl_[4];
            ldsm_x4(ph_, smb + FP_H + pw + aoffP + (uint32_t)(32 * ks));
            ldsm_x4(pl_, smb + FP_L + pw + aoffP + (uint32_t)(32 * ks));
            const uint32_t vrow = (uint32_t)(ks * 16 * FQ_STR);
#pragma unroll
            for (int J = 0; J < 8; J++) {
                uint32_t va = vrow + (uint32_t)(J * 32) + toffV;
                ldsm_x4_t(vh_, smb + FV_H + va);
                mma_bf16(oacc[2 * J + 0], ph_, vh_[0], vh_[1]);
                mma_bf16(oacc[2 * J + 1], ph_, vh_[2], vh_[3]);
                mma_bf16(oacc[2 * J + 0], pl_, vh_[0], vh_[1]);
                mma_bf16(oacc[2 * J + 1], pl_, vh_[2], vh_[3]);
                ldsm_x4_t(vl_, smb + FV_L + va);
                mma_bf16(oacc[2 * J + 0], ph_, vl_[0], vl_[1]);
                mma_bf16(oacc[2 * J + 1], ph_, vl_[2], vl_[3]);
            }
        }
    }

    // ---- normalize + write O (fp32) ----
    const float inv0 = 1.f / l0, inv1 = 1.f / l1;
    const int r0g = qt * 128 + wid * 16 + g;
#pragma unroll
    for (int f = 0; f < 16; f++) {
        int col = 8 * f + 2 * cq;
        size_t b0a = (rowbase + r0g) * DIM + coloff + col;
        size_t b1a = (rowbase + r0g + 8) * DIM + coloff + col;
        *reinterpret_cast<float2*>(&O[b0a]) =
            make_float2(oacc[f][0] * inv0, oacc[f][1] * inv0);
        *reinterpret_cast<float2*>(&O[b1a]) =
            make_float2(oacc[f][2] * inv1, oacc[f][3] * inv1);
    }
}

// ============================================================================
// Launch
// ============================================================================
extern "C" void kernel_launch(void* const* d_in, const int* in_sizes, int n_in,
                              void* d_out, int out_size)
{
    (void)in_sizes; (void)n_in; (void)out_size;
    const float* x  = (const float*)d_in[0];
    const float* Wq = (const float*)d_in[1];
    const float* Wk = (const float*)d_in[2];
    const float* Wv = (const float*)d_in[3];
    const float* Wo = (const float*)d_in[4];
    float* out = (float*)d_out;

    float *Qp, *Kp, *Vp, *Op;
    __nv_bfloat16 *ah, *al, *bh, *bl, *qh, *ql, *kh, *kl, *vh, *vl;
    cudaGetSymbolAddress((void**)&Qp, g_Q);
    cudaGetSymbolAddress((void**)&Kp, g_K);
    cudaGetSymbolAddress((void**)&Vp, g_V);
    cudaGetSymbolAddress((void**)&Op, g_O);
    cudaGetSymbolAddress((void**)&ah, g_ah);
    cudaGetSymbolAddress((void**)&al, g_al);
    cudaGetSymbolAddress((void**)&bh, g_bh);
    cudaGetSymbolAddress((void**)&bl, g_bl);
    cudaGetSymbolAddress((void**)&qh, g_qh);
    cudaGetSymbolAddress((void**)&ql, g_ql);
    cudaGetSymbolAddress((void**)&kh, g_kh);
    cudaGetSymbolAddress((void**)&kl, g_kl);
    cudaGetSymbolAddress((void**)&vh, g_vh);
    cudaGetSymbolAddress((void**)&vl, g_vl);

    cudaFuncSetAttribute(gemm_mma, cudaFuncAttributeMaxDynamicSharedMemorySize,
                         G_SMEM);
    cudaFuncSetAttribute(flash_mma, cudaFuncAttributeMaxDynamicSharedMemorySize,
                         F_SMEM);

    const dim3 ggrid(DIM / 128, MTOT / 128);   // (16, 32)
    const int nx4 = (int)(ELEMS / 4);
    const int nw4 = (int)(((size_t)DIM * DIM) / 4);

    init_invfreq<<<1, 64>>>();

    // QKV projections
    split_bf16<<<(nx4 + 255) / 256, 256>>>(x, ah, al, nx4);
    split_bf16<<<(nw4 + 255) / 256, 256>>>(Wq, bh, bl, nw4);
    gemm_mma<<<ggrid, 256, G_SMEM>>>(ah, al, bh, bl, Qp, MTOT, DIM, DIM);
    split_bf16<<<(nw4 + 255) / 256, 256>>>(Wk, bh, bl, nw4);
    gemm_mma<<<ggrid, 256, G_SMEM>>>(ah, al, bh, bl, Kp, MTOT, DIM, DIM);
    split_bf16<<<(nw4 + 255) / 256, 256>>>(Wv, bh, bl, nw4);
    gemm_mma<<<ggrid, 256, G_SMEM>>>(ah, al, bh, bl, Vp, MTOT, DIM, DIM);

    // RoPE fused with bf16 split; V plain split
    int rope_threads = BATCH * SEQ * NHEAD * 64;
    rope_split<<<rope_threads / 256, 256>>>(Qp, qh, ql);
    rope_split<<<rope_threads / 256, 256>>>(Kp, kh, kl);
    split_bf16<<<(nx4 + 255) / 256, 256>>>(Vp, vh, vl, nx4);

    // Tensor-core causal flash attention
    flash_mma<<<dim3(SEQ / 128, NHEAD, BATCH), 256, F_SMEM>>>(qh, ql, kh, kl,
                                                              vh, vl, Op);

    // Output projection
    split_bf16<<<(nx4 + 255) / 256, 256>>>(Op, ah, al, nx4);
    split_bf16<<<(nw4 + 255) / 256, 256>>>(Wo, bh, bl, nw4);
    gemm_mma<<<ggrid, 256, G_SMEM>>>(ah, al, bh, bl, out, MTOT, DIM, DIM);
}

// round 10
// speedup vs baseline: 3.2184x; 1.0809x over previous
#include <cuda_runtime.h>
#include <cuda_bf16.h>
#include <math.h>
#include <stdint.h>

// Problem constants
#define BATCH 2
#define SEQ   2048
#define DIM   2048
#define NHEAD 16
#define HDIM  128
#define MTOT  (BATCH * SEQ)      // 4096 rows
#define ELEMS ((size_t)BATCH * SEQ * DIM)   // 8388608

// ---------------- scratch (no allocations allowed) ----------------
__device__ float g_Q[ELEMS];
__device__ float g_K[ELEMS];
__device__ __align__(16) __nv_bfloat16 g_ah[ELEMS];              // A hi (x, then attn-out)
__device__ __align__(16) __nv_bfloat16 g_al[ELEMS];              // A lo
__device__ __align__(16) __nv_bfloat16 g_bh[(size_t)DIM * DIM];  // W hi
__device__ __align__(16) __nv_bfloat16 g_bl[(size_t)DIM * DIM];  // W lo
__device__ __align__(16) __nv_bfloat16 g_qh[ELEMS];
__device__ __align__(16) __nv_bfloat16 g_ql[ELEMS];
__device__ __align__(16) __nv_bfloat16 g_kh[ELEMS];
__device__ __align__(16) __nv_bfloat16 g_kl[ELEMS];
__device__ __align__(16) __nv_bfloat16 g_vh[ELEMS];
__device__ __align__(16) __nv_bfloat16 g_vl[ELEMS];
__device__ double g_invfreq[64];

// ============================================================================
// mma.sync / ldmatrix / cp.async helpers (all legal at compute_103)
// ============================================================================
__device__ __forceinline__ uint32_t smem_u32(const void* p) {
    uint32_t a;
    asm("{ .reg .u64 t; cvta.to.shared.u64 t, %1; cvt.u32.u64 %0, t; }"
        : "=r"(a) : "l"(p));
    return a;
}

__device__ __forceinline__ void ldsm_x4(uint32_t (&r)[4], uint32_t addr) {
    asm volatile("ldmatrix.sync.aligned.m8n8.x4.shared.b16 {%0,%1,%2,%3}, [%4];"
                 : "=r"(r[0]), "=r"(r[1]), "=r"(r[2]), "=r"(r[3]) : "r"(addr));
}

__device__ __forceinline__ void ldsm_x4_t(uint32_t (&r)[4], uint32_t addr) {
    asm volatile("ldmatrix.sync.aligned.m8n8.x4.trans.shared.b16 {%0,%1,%2,%3}, [%4];"
                 : "=r"(r[0]), "=r"(r[1]), "=r"(r[2]), "=r"(r[3]) : "r"(addr));
}

__device__ __forceinline__ void mma_bf16(float (&c)[4], const uint32_t (&a)[4],
                                         uint32_t b0, uint32_t b1) {
    asm volatile(
        "mma.sync.aligned.m16n8k16.row.col.f32.bf16.bf16.f32 "
        "{%0,%1,%2,%3}, {%4,%5,%6,%7}, {%8,%9}, {%0,%1,%2,%3};"
        : "+f"(c[0]), "+f"(c[1]), "+f"(c[2]), "+f"(c[3])
        : "r"(a[0]), "r"(a[1]), "r"(a[2]), "r"(a[3]), "r"(b0), "r"(b1));
}

#define CP_ASYNC16(dst, src) \
    asm volatile("cp.async.ca.shared.global [%0], [%1], 16;" \
                 :: "r"(dst), "l"(src) : "memory")
#define CP_COMMIT() asm volatile("cp.async.commit_group;" ::: "memory")
#define CP_WAIT0()  asm volatile("cp.async.wait_group 0;" ::: "memory")
#define CP_WAIT1()  asm volatile("cp.async.wait_group 1;" ::: "memory")

// hi/lo bf16 pair packing
__device__ __forceinline__ void split2pack(float a, float b, uint32_t& h, uint32_t& l) {
    __nv_bfloat16 ha = __float2bfloat16(a), hb = __float2bfloat16(b);
    __nv_bfloat162 th(ha, hb);
    h = *reinterpret_cast<uint32_t*>(&th);
    __nv_bfloat162 tl(__float2bfloat16(a - __bfloat162float(ha)),
                      __float2bfloat16(b - __bfloat162float(hb)));
    l = *reinterpret_cast<uint32_t*>(&tl);
}

// ============================================================================
// bf16x3 tensor-core GEMM (NT): C[m,n] = sum_k A[m,k]*B[n,k]
// CTA tile 256x128, BK=32, 512 threads = 16 warps (8m x 2n), warp tile 32x64.
// Double-buffered cp.async; smem row stride 40 bf16 (80B, conflict-free).
// Optional fused bf16 hi/lo output (Chi/Clo non-null -> skip fp32 C).
// ============================================================================
#define G_A_T (256 * 80)                  // 20480 B per A tile
#define G_B_T (128 * 80)                  // 10240 B per B tile
#define TA_H 0
#define TA_L (G_A_T)
#define TB_H (2 * G_A_T)
#define TB_L (2 * G_A_T + G_B_T)
#define G_STAGE (2 * G_A_T + 2 * G_B_T)   // 61440
#define G_SMEM (2 * G_STAGE)              // 122880

__global__ __launch_bounds__(512, 1)
void gemm_mma(const __nv_bfloat16* __restrict__ Ah, const __nv_bfloat16* __restrict__ Al,
              const __nv_bfloat16* __restrict__ Bh, const __nv_bfloat16* __restrict__ Bl,
              float* __restrict__ C, __nv_bfloat16* __restrict__ Chi,
              __nv_bfloat16* __restrict__ Clo, int M, int N, int K)
{
    extern __shared__ __align__(16) char sm[];
    const uint32_t smb = smem_u32(sm);
    const int tid = threadIdx.x;
    const int wid = tid >> 5, lane = tid & 31;
    const int wm = wid & 7, wn = wid >> 3;            // 8 x 2 warp grid
    const int m0 = blockIdx.y * 256, n0 = blockIdx.x * 128;

    const uint32_t aoff = (uint32_t)(((lane & 7) + 8 * ((lane >> 3) & 1)) * 80
                                     + 16 * (lane >> 4));
    const uint32_t boff = (uint32_t)(((lane & 7) + 8 * (lane >> 4)) * 80
                                     + 16 * ((lane >> 3) & 1));

    const int ar0 = tid >> 2, ac = (tid & 3);         // A rows 0..127 (+128)
    const int br0 = tid >> 2;                         // B rows 0..127

    auto load_tiles = [&](int kb, int st) {
        uint32_t base = smb + (uint32_t)(st * G_STAGE);
        uint32_t soA0 = (uint32_t)(ar0 * 80 + ac * 16);
        uint32_t soA1 = soA0 + (uint32_t)(128 * 80);
        uint32_t soB  = (uint32_t)(br0 * 80 + ac * 16);
        size_t gA0 = (size_t)(m0 + ar0) * K + (size_t)kb * 32 + ac * 8;
        size_t gA1 = (size_t)(m0 + ar0 + 128) * K + (size_t)kb * 32 + ac * 8;
        size_t gB  = (size_t)(n0 + br0) * K + (size_t)kb * 32 + ac * 8;
        CP_ASYNC16(base + TA_H + soA0, Ah + gA0);
        CP_ASYNC16(base + TA_H + soA1, Ah + gA1);
        CP_ASYNC16(base + TA_L + soA0, Al + gA0);
        CP_ASYNC16(base + TA_L + soA1, Al + gA1);
        CP_ASYNC16(base + TB_H + soB, Bh + gB);
        CP_ASYNC16(base + TB_L + soB, Bl + gB);
        CP_COMMIT();
    };

    float acc[2][8][4];
#pragma unroll
    for (int i = 0; i < 2; i++)
#pragma unroll
        for (int j = 0; j < 8; j++)
#pragma unroll
            for (int v = 0; v < 4; v++) acc[i][j][v] = 0.f;

    const int KB = K >> 5;
    load_tiles(0, 0);
    int st = 0;
    for (int kb = 0; kb < KB; kb++) {
        CP_WAIT0();
        __syncthreads();
        if (kb + 1 < KB) load_tiles(kb + 1, st ^ 1);

        const uint32_t sb = smb + (uint32_t)(st * G_STAGE);
#pragma unroll
        for (int ks = 0; ks < 2; ks++) {
            const uint32_t kso = (uint32_t)(32 * ks);
            uint32_t ah_[2][4], al_[2][4], bb[4][4];
#pragma unroll
            for (int f = 0; f < 2; f++) {
                uint32_t ro = (uint32_t)((wm * 32 + 16 * f) * 80);
                ldsm_x4(ah_[f], sb + TA_H + ro + aoff + kso);
                ldsm_x4(al_[f], sb + TA_L + ro + aoff + kso);
            }
#pragma unroll
            for (int j = 0; j < 4; j++) {
                uint32_t ro = (uint32_t)((wn * 64 + 16 * j) * 80);
                ldsm_x4(bb[j], sb + TB_H + ro + boff + kso);
            }
            // hi*hi : 16 independent accumulators before any reuse
#pragma unroll
            for (int f = 0; f < 2; f++)
#pragma unroll
                for (int j = 0; j < 4; j++) {
                    mma_bf16(acc[f][2 * j + 0], ah_[f], bb[j][0], bb[j][1]);
                    mma_bf16(acc[f][2 * j + 1], ah_[f], bb[j][2], bb[j][3]);
                }
            // lo*hi
#pragma unroll
            for (int f = 0; f < 2; f++)
#pragma unroll
                for (int j = 0; j < 4; j++) {
                    mma_bf16(acc[f][2 * j + 0], al_[f], bb[j][0], bb[j][1]);
                    mma_bf16(acc[f][2 * j + 1], al_[f], bb[j][2], bb[j][3]);
                }
            // hi*lo
#pragma unroll
            for (int j = 0; j < 4; j++) {
                uint32_t ro = (uint32_t)((wn * 64 + 16 * j) * 80);
                ldsm_x4(bb[j], sb + TB_L + ro + boff + kso);
            }
#pragma unroll
            for (int f = 0; f < 2; f++)
#pragma unroll
                for (int j = 0; j < 4; j++) {
                    mma_bf16(acc[f][2 * j + 0], ah_[f], bb[j][0], bb[j][1]);
                    mma_bf16(acc[f][2 * j + 1], ah_[f], bb[j][2], bb[j][3]);
                }
        }
        st ^= 1;
    }

    const int g = lane >> 2, cq = lane & 3;
    if (Chi) {
#pragma unroll
        for (int f = 0; f < 2; f++)
#pragma unroll
            for (int j = 0; j < 8; j++) {
                int row = m0 + wm * 32 + 16 * f + g;
                int col = n0 + wn * 64 + 8 * j + 2 * cq;
                uint32_t h0, l0, h1, l1;
                split2pack(acc[f][j][0], acc[f][j][1], h0, l0);
                split2pack(acc[f][j][2], acc[f][j][3], h1, l1);
                *reinterpret_cast<uint32_t*>(&Chi[(size_t)row * N + col]) = h0;
                *reinterpret_cast<uint32_t*>(&Clo[(size_t)row * N + col]) = l0;
                *reinterpret_cast<uint32_t*>(&Chi[(size_t)(row + 8) * N + col]) = h1;
                *reinterpret_cast<uint32_t*>(&Clo[(size_t)(row + 8) * N + col]) = l1;
            }
    } else {
#pragma unroll
        for (int f = 0; f < 2; f++)
#pragma unroll
            for (int j = 0; j < 8; j++) {
                int row = m0 + wm * 32 + 16 * f + g;
                int col = n0 + wn * 64 + 8 * j + 2 * cq;
                *reinterpret_cast<float2*>(&C[(size_t)row * N + col]) =
                    make_float2(acc[f][j][0], acc[f][j][1]);
                *reinterpret_cast<float2*>(&C[(size_t)(row + 8) * N + col]) =
                    make_float2(acc[f][j][2], acc[f][j][3]);
            }
    }
}

// ============================================================================
// fp32 -> bf16 hi/lo split
// ============================================================================
__global__ __launch_bounds__(256)
void split_bf16(const float* __restrict__ in, __nv_bfloat16* __restrict__ hi,
                __nv_bfloat16* __restrict__ lo, int n4)
{
    int i = blockIdx.x * blockDim.x + threadIdx.x;
    if (i >= n4) return;
    float4 v = *reinterpret_cast<const float4*>(in + (size_t)i * 4);
    uint32_t h0, l0, h1, l1;
    split2pack(v.x, v.y, h0, l0);
    split2pack(v.z, v.w, h1, l1);
    uint32_t* H = reinterpret_cast<uint32_t*>(hi) + (size_t)i * 2;
    uint32_t* L = reinterpret_cast<uint32_t*>(lo) + (size_t)i * 2;
    H[0] = h0; H[1] = h1; L[0] = l0; L[1] = l1;
}

// ============================================================================
// RoPE fused with bf16 hi/lo split; handles Q (y=0) and K (y=1) in one launch.
// ============================================================================
__global__ void init_invfreq()
{
    int i = threadIdx.x;
    g_invfreq[i] = exp(-(double)i * (9.210340371976184 / 64.0));
}

__global__ __launch_bounds__(256)
void rope_split(const float* __restrict__ Qf, const float* __restrict__ Kf,
                __nv_bfloat16* __restrict__ Qhi, __nv_bfloat16* __restrict__ Qlo,
                __nv_bfloat16* __restrict__ Khi, __nv_bfloat16* __restrict__ Klo)
{
    const float* in = blockIdx.y ? Kf : Qf;
    __nv_bfloat16* hi = blockIdx.y ? Khi : Qhi;
    __nv_bfloat16* lo = blockIdx.y ? Klo : Qlo;

    int idx = blockIdx.x * blockDim.x + threadIdx.x;  // [0, B*S*H*64)
    int i = idx & 63;
    int h = (idx >> 6) & (NHEAD - 1);
    int s = (idx >> 10) & (SEQ - 1);
    int b = idx >> 21;

    double inv = g_invfreq[i];
    float ang = (float)((double)s * inv);
    float c, sn;
    sincosf(ang, &sn, &c);

    size_t base = ((size_t)b * SEQ + s) * DIM + (size_t)h * HDIM;
    float x1 = in[base + i];
    float x2 = in[base + 64 + i];
    float y1 = x1 * c - x2 * sn;
    float y2 = x1 * sn + x2 * c;

    __nv_bfloat16 h1 = __float2bfloat16(y1);
    __nv_bfloat16 h2 = __float2bfloat16(y2);
    hi[base + i]      = h1;
    hi[base + 64 + i] = h2;
    lo[base + i]      = __float2bfloat16(y1 - __bfloat162float(h1));
    lo[base + 64 + i] = __float2bfloat16(y2 - __bfloat162float(h2));
}

// ============================================================================
// Tensor-core causal flash attention, bf16x3, fp32 softmax, register P,
// cp.async pipelined K/V. CTA: 128 q-rows; 256 threads = 8 warps x 16 rows.
// Output written directly as bf16 hi/lo (feeds the Wo GEMM).
// smem: Q hi/lo 128x272B, K hi/lo 64x272B, V hi/lo 64x272B = 139264 B.
// ============================================================================
#define FQ_STR 272
#define FQ_H 0
#define FQ_L (FQ_H + 128 * FQ_STR)     // 34816
#define FK_H (FQ_L + 128 * FQ_STR)     // 69632
#define FK_L (FK_H + 64 * FQ_STR)      // 87040
#define FV_H (FK_L + 64 * FQ_STR)      // 104448
#define FV_L (FV_H + 64 * FQ_STR)      // 121856
#define F_SMEM (FV_L + 64 * FQ_STR)    // 139264

__global__ __launch_bounds__(256, 1)
void flash_mma(const __nv_bfloat16* __restrict__ Qh, const __nv_bfloat16* __restrict__ Ql,
               const __nv_bfloat16* __restrict__ Kh, const __nv_bfloat16* __restrict__ Kl,
               const __nv_bfloat16* __restrict__ Vh, const __nv_bfloat16* __restrict__ Vl,
               __nv_bfloat16* __restrict__ Ohi, __nv_bfloat16* __restrict__ Olo)
{
    extern __shared__ __align__(16) char sm[];
    const uint32_t smb = smem_u32(sm);
    const int qt = (int)gridDim.x - 1 - (int)blockIdx.x;  // big tiles first
    const int h  = blockIdx.y;
    const int b  = blockIdx.z;
    const int tid = threadIdx.x;
    const int wid = tid >> 5, lane = tid & 31;
    const int g = lane >> 2, cq = lane & 3;
    const float scale = 0.08838834764831845f;   // 1/sqrt(128)

    const uint32_t aoffQ = (uint32_t)(((lane & 7) + 8 * ((lane >> 3) & 1)) * FQ_STR
                                      + 16 * (lane >> 4));
    const uint32_t boffK = (uint32_t)(((lane & 7) + 8 * (lane >> 4)) * FQ_STR
                                      + 16 * ((lane >> 3) & 1));
    const uint32_t toffV = (uint32_t)(((lane & 7) + 8 * ((lane >> 3) & 1)) * FQ_STR
                                      + 16 * (lane >> 4));

    const size_t rowbase = (size_t)b * SEQ;
    const size_t coloff = (size_t)h * HDIM;
    const int KT = 2 * qt + 2;

    auto load_kv = [&](int kt, bool isK) {
#pragma unroll
        for (int i = 0; i < 4; i++) {
            int s = tid + i * 256;              // 0..1023
            int r = s >> 4, c = s & 15;
            uint32_t so = (uint32_t)(r * FQ_STR + c * 16);
            size_t ga = (rowbase + kt * 64 + r) * DIM + coloff + c * 8;
            if (isK) {
                CP_ASYNC16(smb + FK_H + so, Kh + ga);
                CP_ASYNC16(smb + FK_L + so, Kl + ga);
            } else {
                CP_ASYNC16(smb + FV_H + so, Vh + ga);
                CP_ASYNC16(smb + FV_L + so, Vl + ga);
            }
        }
    };

    // Prologue: group A = Q + K(0); group B = V(0)
#pragma unroll
    for (int i = 0; i < 8; i++) {
        int s = tid + i * 256;                  // 0..2047
        int r = s >> 4, c = s & 15;
        uint32_t so = (uint32_t)(r * FQ_STR + c * 16);
        size_t ga = (rowbase + qt * 128 + r) * DIM + coloff + c * 8;
        CP_ASYNC16(smb + FQ_H + so, Qh + ga);
        CP_ASYNC16(smb + FQ_L + so, Ql + ga);
    }
    load_kv(0, true);
    CP_COMMIT();
    load_kv(0, false);
    CP_COMMIT();

    float oacc[16][4];
#pragma unroll
    for (int f = 0; f < 16; f++)
#pragma unroll
        for (int v = 0; v < 4; v++) oacc[f][v] = 0.f;
    float m0 = -1e30f, m1 = -1e30f, l0 = 0.f, l1 = 0.f;

    for (int kt = 0; kt < KT; kt++) {
        const int ktn = (kt + 1 < KT) ? kt + 1 : kt;

        CP_WAIT1();            // K(kt) (and Q at kt=0) landed
        __syncthreads();

        // ---- S = Q K^T (bf16x3), reordered for acc distance ----
        float sacc[8][4];
#pragma unroll
        for (int j = 0; j < 8; j++)
#pragma unroll
            for (int v = 0; v < 4; v++) sacc[j][v] = 0.f;

        const uint32_t qrow = (uint32_t)(wid * 16 * FQ_STR);
#pragma unroll
        for (int ks = 0; ks < 8; ks++) {
            const uint32_t kso = (uint32_t)(32 * ks);
            uint32_t ah_[4], al_[4], bh_[4][4];
            ldsm_x4(ah_, smb + FQ_H + qrow + aoffQ + kso);
            ldsm_x4(al_, smb + FQ_L + qrow + aoffQ + kso);
#pragma unroll
            for (int J = 0; J < 4; J++)
                ldsm_x4(bh_[J], smb + FK_H + (uint32_t)(J * 16 * FQ_STR) + boffK + kso);
#pragma unroll
            for (int J = 0; J < 4; J++) {
                mma_bf16(sacc[2 * J + 0], ah_, bh_[J][0], bh_[J][1]);
                mma_bf16(sacc[2 * J + 1], ah_, bh_[J][2], bh_[J][3]);
            }
#pragma unroll
            for (int J = 0; J < 4; J++) {
                mma_bf16(sacc[2 * J + 0], al_, bh_[J][0], bh_[J][1]);
                mma_bf16(sacc[2 * J + 1], al_, bh_[J][2], bh_[J][3]);
            }
#pragma unroll
            for (int J = 0; J < 4; J++) {
                uint32_t bl_[4];
                ldsm_x4(bl_, smb + FK_L + (uint32_t)(J * 16 * FQ_STR) + boffK + kso);
                mma_bf16(sacc[2 * J + 0], ah_, bl_[0], bl_[1]);
                mma_bf16(sacc[2 * J + 1], ah_, bl_[2], bl_[3]);
            }
        }
        __syncthreads();       // all warps done with K smem
        load_kv(ktn, true);    // prefetch K(kt+1) during softmax+PV
        CP_COMMIT();

        // ---- scale + causal mask ----
        const int row0 = qt * 128 + wid * 16 + g;
        const int row1 = row0 + 8;
        const bool diag = (kt >= 2 * qt);
#pragma unroll
        for (int j = 0; j < 8; j++) {
            int colb = kt * 64 + 8 * j + 2 * cq;
#pragma unroll
            for (int v = 0; v < 4; v++) sacc[j][v] *= scale;
            if (diag) {
                if (colb     > row0) sacc[j][0] = -1e30f;
                if (colb + 1 > row0) sacc[j][1] = -1e30f;
                if (colb     > row1) sacc[j][2] = -1e30f;
                if (colb + 1 > row1) sacc[j][3] = -1e30f;
            }
        }

        // ---- online softmax + register-resident P fragments ----
        float mt0 = -1e30f, mt1 = -1e30f;
#pragma unroll
        for (int j = 0; j < 8; j++) {
            mt0 = fmaxf(mt0, fmaxf(sacc[j][0], sacc[j][1]));
            mt1 = fmaxf(mt1, fmaxf(sacc[j][2], sacc[j][3]));
        }
        mt0 = fmaxf(mt0, __shfl_xor_sync(0xffffffffu, mt0, 1));
        mt0 = fmaxf(mt0, __shfl_xor_sync(0xffffffffu, mt0, 2));
        mt1 = fmaxf(mt1, __shfl_xor_sync(0xffffffffu, mt1, 1));
        mt1 = fmaxf(mt1, __shfl_xor_sync(0xffffffffu, mt1, 2));

        float mn0 = fmaxf(m0, mt0), mn1 = fmaxf(m1, mt1);
        float a0 = __expf(m0 - mn0), a1 = __expf(m1 - mn1);
        m0 = mn0; m1 = mn1;

        uint32_t ph0[8], ph1[8], pl0[8], pl1[8];
        float ls0 = 0.f, ls1 = 0.f;
#pragma unroll
        for (int j = 0; j < 8; j++) {
            float p0 = __expf(sacc[j][0] - mn0);
            float p1 = __expf(sacc[j][1] - mn0);
            float p2 = __expf(sacc[j][2] - mn1);
            float p3 = __expf(sacc[j][3] - mn1);
            ls0 += p0 + p1; ls1 += p2 + p3;
            split2pack(p0, p1, ph0[j], pl0[j]);
            split2pack(p2, p3, ph1[j], pl1[j]);
        }
        ls0 += __shfl_xor_sync(0xffffffffu, ls0, 1);
        ls0 += __shfl_xor_sync(0xffffffffu, ls0, 2);
        ls1 += __shfl_xor_sync(0xffffffffu, ls1, 1);
        ls1 += __shfl_xor_sync(0xffffffffu, ls1, 2);
        l0 = l0 * a0 + ls0;
        l1 = l1 * a1 + ls1;
#pragma unroll
        for (int f = 0; f < 16; f++) {
            oacc[f][0] *= a0; oacc[f][1] *= a0;
            oacc[f][2] *= a1; oacc[f][3] *= a1;
        }

        CP_WAIT1();            // V(kt) landed
        __syncthreads();

        // ---- O += P V (bf16x3, register P) ----
#pragma unroll
        for (int ks = 0; ks < 4; ks++) {
            uint32_t a_h[4] = {ph0[2 * ks], ph1[2 * ks], ph0[2 * ks + 1], ph1[2 * ks + 1]};
            uint32_t a_l[4] = {pl0[2 * ks], pl1[2 * ks], pl0[2 * ks + 1], pl1[2 * ks + 1]};
            const uint32_t vrow = (uint32_t)(ks * 16 * FQ_STR);
            uint32_t vv[8][4];
#pragma unroll
            for (int J = 0; J < 8; J++)
                ldsm_x4_t(vv[J], smb + FV_H + vrow + (uint32_t)(J * 32) + toffV);
#pragma unroll
            for (int J = 0; J < 8; J++) {
                mma_bf16(oacc[2 * J + 0], a_h, vv[J][0], vv[J][1]);
                mma_bf16(oacc[2 * J + 1], a_h, vv[J][2], vv[J][3]);
            }
#pragma unroll
            for (int J = 0; J < 8; J++) {
                mma_bf16(oacc[2 * J + 0], a_l, vv[J][0], vv[J][1]);
                mma_bf16(oacc[2 * J + 1], a_l, vv[J][2], vv[J][3]);
            }
#pragma unroll
            for (int J = 0; J < 8; J++)
                ldsm_x4_t(vv[J], smb + FV_L + vrow + (uint32_t)(J * 32) + toffV);
#pragma unroll
            for (int J = 0; J < 8; J++) {
                mma_bf16(oacc[2 * J + 0], a_h, vv[J][0], vv[J][1]);
                mma_bf16(oacc[2 * J + 1], a_h, vv[J][2], vv[J][3]);
            }
        }
        __syncthreads();       // all warps done with V smem
        load_kv(ktn, false);   // prefetch V(kt+1) during next QK
        CP_COMMIT();
    }
    CP_WAIT0();

    // ---- normalize + write O as bf16 hi/lo ----
    const float inv0 = 1.f / l0, inv1 = 1.f / l1;
    const int r0g = qt * 128 + wid * 16 + g;
#pragma unroll
    for (int f = 0; f < 16; f++) {
        int col = 8 * f + 2 * cq;
        size_t b0a = (rowbase + r0g) * DIM + coloff + col;
        size_t b1a = (rowbase + r0g + 8) * DIM + coloff + col;
        uint32_t h0, lo0, h1, lo1;
        split2pack(oacc[f][0] * inv0, oacc[f][1] * inv0, h0, lo0);
        split2pack(oacc[f][2] * inv1, oacc[f][3] * inv1, h1, lo1);
        *reinterpret_cast<uint32_t*>(&Ohi[b0a]) = h0;
        *reinterpret_cast<uint32_t*>(&Olo[b0a]) = lo0;
        *reinterpret_cast<uint32_t*>(&Ohi[b1a]) = h1;
        *reinterpret_cast<uint32_t*>(&Olo[b1a]) = lo1;
    }
}

// ============================================================================
// Launch
// ============================================================================
extern "C" void kernel_launch(void* const* d_in, const int* in_sizes, int n_in,
                              void* d_out, int out_size)
{
    (void)in_sizes; (void)n_in; (void)out_size;
    const float* x  = (const float*)d_in[0];
    const float* Wq = (const float*)d_in[1];
    const float* Wk = (const float*)d_in[2];
    const float* Wv = (const float*)d_in[3];
    const float* Wo = (const float*)d_in[4];
    float* out = (float*)d_out;

    float *Qp, *Kp;
    __nv_bfloat16 *ah, *al, *bh, *bl, *qh, *ql, *kh, *kl, *vh, *vl;
    cudaGetSymbolAddress((void**)&Qp, g_Q);
    cudaGetSymbolAddress((void**)&Kp, g_K);
    cudaGetSymbolAddress((void**)&ah, g_ah);
    cudaGetSymbolAddress((void**)&al, g_al);
    cudaGetSymbolAddress((void**)&bh, g_bh);
    cudaGetSymbolAddress((void**)&bl, g_bl);
    cudaGetSymbolAddress((void**)&qh, g_qh);
    cudaGetSymbolAddress((void**)&ql, g_ql);
    cudaGetSymbolAddress((void**)&kh, g_kh);
    cudaGetSymbolAddress((void**)&kl, g_kl);
    cudaGetSymbolAddress((void**)&vh, g_vh);
    cudaGetSymbolAddress((void**)&vl, g_vl);

    cudaFuncSetAttribute(gemm_mma, cudaFuncAttributeMaxDynamicSharedMemorySize,
                         G_SMEM);
    cudaFuncSetAttribute(flash_mma, cudaFuncAttributeMaxDynamicSharedMemorySize,
                         F_SMEM);

    const dim3 ggrid(DIM / 128, MTOT / 256);   // (16, 16)
    const int nx4 = (int)(ELEMS / 4);
    const int nw4 = (int)(((size_t)DIM * DIM) / 4);

    init_invfreq<<<1, 64>>>();

    // QKV projections (V emits bf16 hi/lo directly)
    split_bf16<<<(nx4 + 255) / 256, 256>>>(x, ah, al, nx4);
    split_bf16<<<(nw4 + 255) / 256, 256>>>(Wq, bh, bl, nw4);
    gemm_mma<<<ggrid, 512, G_SMEM>>>(ah, al, bh, bl, Qp, nullptr, nullptr,
                                     MTOT, DIM, DIM);
    split_bf16<<<(nw4 + 255) / 256, 256>>>(Wk, bh, bl, nw4);
    gemm_mma<<<ggrid, 512, G_SMEM>>>(ah, al, bh, bl, Kp, nullptr, nullptr,
                                     MTOT, DIM, DIM);
    split_bf16<<<(nw4 + 255) / 256, 256>>>(Wv, bh, bl, nw4);
    gemm_mma<<<ggrid, 512, G_SMEM>>>(ah, al, bh, bl, nullptr, vh, vl,
                                     MTOT, DIM, DIM);

    // RoPE + split for Q and K in one launch
    int rope_blocks = (BATCH * SEQ * NHEAD * 64) / 256;   // 16384
    rope_split<<<dim3(rope_blocks, 2), 256>>>(Qp, Kp, qh, ql, kh, kl);

    // Tensor-core causal flash attention -> writes ah/al (bf16 hi/lo)
    flash_mma<<<dim3(SEQ / 128, NHEAD, BATCH), 256, F_SMEM>>>(qh, ql, kh, kl,
                                                              vh, vl, ah, al);

    // Output projection
    split_bf16<<<(nw4 + 255) / 256, 256>>>(Wo, bh, bl, nw4);
    gemm_mma<<<ggrid, 512, G_SMEM>>>(ah, al, bh, bl, out, nullptr, nullptr,
                                     MTOT, DIM, DIM);
}

// round 11
// speedup vs baseline: 3.2415x; 1.0072x over previous
#include <cuda_runtime.h>
#include <cuda_bf16.h>
#include <math.h>
#include <stdint.h>

// Problem constants
#define BATCH 2
#define SEQ   2048
#define DIM   2048
#define NHEAD 16
#define HDIM  128
#define MTOT  (BATCH * SEQ)      // 4096 rows
#define ELEMS ((size_t)BATCH * SEQ * DIM)   // 8388608

// ---------------- scratch (no allocations allowed) ----------------
__device__ float g_Q[ELEMS];
__device__ float g_K[ELEMS];
__device__ __align__(16) __nv_bfloat16 g_ah[ELEMS];              // A hi (x, then attn-out)
__device__ __align__(16) __nv_bfloat16 g_al[ELEMS];              // A lo
__device__ __align__(16) __nv_bfloat16 g_bh[(size_t)DIM * DIM];  // W hi
__device__ __align__(16) __nv_bfloat16 g_bl[(size_t)DIM * DIM];  // W lo
__device__ __align__(16) __nv_bfloat16 g_qh[ELEMS];
__device__ __align__(16) __nv_bfloat16 g_ql[ELEMS];
__device__ __align__(16) __nv_bfloat16 g_kh[ELEMS];
__device__ __align__(16) __nv_bfloat16 g_kl[ELEMS];
__device__ __align__(16) __nv_bfloat16 g_vh[ELEMS];
__device__ __align__(16) __nv_bfloat16 g_vl[ELEMS];
__device__ double g_invfreq[64];

// ============================================================================
// mma.sync / ldmatrix / cp.async helpers (all legal at compute_103)
// ============================================================================
__device__ __forceinline__ uint32_t smem_u32(const void* p) {
    uint32_t a;
    asm("{ .reg .u64 t; cvta.to.shared.u64 t, %1; cvt.u32.u64 %0, t; }"
        : "=r"(a) : "l"(p));
    return a;
}

__device__ __forceinline__ void ldsm_x4(uint32_t (&r)[4], uint32_t addr) {
    asm volatile("ldmatrix.sync.aligned.m8n8.x4.shared.b16 {%0,%1,%2,%3}, [%4];"
                 : "=r"(r[0]), "=r"(r[1]), "=r"(r[2]), "=r"(r[3]) : "r"(addr));
}

__device__ __forceinline__ void ldsm_x4_t(uint32_t (&r)[4], uint32_t addr) {
    asm volatile("ldmatrix.sync.aligned.m8n8.x4.trans.shared.b16 {%0,%1,%2,%3}, [%4];"
                 : "=r"(r[0]), "=r"(r[1]), "=r"(r[2]), "=r"(r[3]) : "r"(addr));
}

__device__ __forceinline__ void mma_bf16(float (&c)[4], const uint32_t (&a)[4],
                                         uint32_t b0, uint32_t b1) {
    asm volatile(
        "mma.sync.aligned.m16n8k16.row.col.f32.bf16.bf16.f32 "
        "{%0,%1,%2,%3}, {%4,%5,%6,%7}, {%8,%9}, {%0,%1,%2,%3};"
        : "+f"(c[0]), "+f"(c[1]), "+f"(c[2]), "+f"(c[3])
        : "r"(a[0]), "r"(a[1]), "r"(a[2]), "r"(a[3]), "r"(b0), "r"(b1));
}

#define CP_ASYNC16(dst, src) \
    asm volatile("cp.async.ca.shared.global [%0], [%1], 16;" \
                 :: "r"(dst), "l"(src) : "memory")
#define CP_COMMIT() asm volatile("cp.async.commit_group;" ::: "memory")
#define CP_WAIT0()  asm volatile("cp.async.wait_group 0;" ::: "memory")
#define CP_WAIT1()  asm volatile("cp.async.wait_group 1;" ::: "memory")

// hi/lo bf16 pair packing
__device__ __forceinline__ void split2pack(float a, float b, uint32_t& h, uint32_t& l) {
    __nv_bfloat16 ha = __float2bfloat16(a), hb = __float2bfloat16(b);
    __nv_bfloat162 th(ha, hb);
    h = *reinterpret_cast<uint32_t*>(&th);
    __nv_bfloat162 tl(__float2bfloat16(a - __bfloat162float(ha)),
                      __float2bfloat16(b - __bfloat162float(hb)));
    l = *reinterpret_cast<uint32_t*>(&tl);
}

// ============================================================================
// bf16x3 tensor-core GEMM (NT): C[m,n] = sum_k A[m,k]*B[n,k]
// CTA tile 128x128, BK=32, 128 threads = 4 warps (2m x 2n), warp tile 64x64.
// 2 CTAs/SM (regs ~200, smem 80KB/CTA). Double-buffered cp.async.
// smem row stride 40 bf16 (80B) -> conflict-free ldmatrix.
// Optional fused bf16 hi/lo output (Chi/Clo non-null -> skip fp32 C).
// ============================================================================
#define G_TILE_B (128 * 80)               // 10240 B per tile
#define TA_H 0
#define TA_L (G_TILE_B)
#define TB_H (2 * G_TILE_B)
#define TB_L (3 * G_TILE_B)
#define G_STAGE (4 * G_TILE_B)            // 40960 per stage
#define G_SMEM (2 * G_STAGE)              // 81920

__global__ __launch_bounds__(128, 2)
void gemm_mma(const __nv_bfloat16* __restrict__ Ah, const __nv_bfloat16* __restrict__ Al,
              const __nv_bfloat16* __restrict__ Bh, const __nv_bfloat16* __restrict__ Bl,
              float* __restrict__ C, __nv_bfloat16* __restrict__ Chi,
              __nv_bfloat16* __restrict__ Clo, int M, int N, int K)
{
    extern __shared__ __align__(16) char sm[];
    const uint32_t smb = smem_u32(sm);
    const int tid = threadIdx.x;
    const int wid = tid >> 5, lane = tid & 31;
    const int wm = wid & 1, wn = wid >> 1;            // 2 x 2 warp grid
    const int m0 = blockIdx.y * 128, n0 = blockIdx.x * 128;

    const uint32_t aoff = (uint32_t)(((lane & 7) + 8 * ((lane >> 3) & 1)) * 80
                                     + 16 * (lane >> 4));
    const uint32_t boff = (uint32_t)(((lane & 7) + 8 * (lane >> 4)) * 80
                                     + 16 * ((lane >> 3) & 1));

    // per-thread load coords: 4 chunks per tile (128 rows x 4 chunks, 128 thr)
    const int lr = tid >> 2, lc = tid & 3;            // row 0..31 (+32*i), chunk

    auto load_tiles = [&](int kb, int st) {
        uint32_t base = smb + (uint32_t)(st * G_STAGE);
#pragma unroll
        for (int i = 0; i < 4; i++) {
            int r = lr + 32 * i;
            uint32_t so = (uint32_t)(r * 80 + lc * 16);
            size_t ga = (size_t)(m0 + r) * K + (size_t)kb * 32 + lc * 8;
            size_t gb = (size_t)(n0 + r) * K + (size_t)kb * 32 + lc * 8;
            CP_ASYNC16(base + TA_H + so, Ah + ga);
            CP_ASYNC16(base + TA_L + so, Al + ga);
            CP_ASYNC16(base + TB_H + so, Bh + gb);
            CP_ASYNC16(base + TB_L + so, Bl + gb);
        }
        CP_COMMIT();
    };

    float acc[4][8][4];
#pragma unroll
    for (int i = 0; i < 4; i++)
#pragma unroll
        for (int j = 0; j < 8; j++)
#pragma unroll
            for (int v = 0; v < 4; v++) acc[i][j][v] = 0.f;

    const int KB = K >> 5;
    load_tiles(0, 0);
    int st = 0;
    for (int kb = 0; kb < KB; kb++) {
        CP_WAIT0();
        __syncthreads();
        if (kb + 1 < KB) load_tiles(kb + 1, st ^ 1);

        const uint32_t sb = smb + (uint32_t)(st * G_STAGE);
#pragma unroll
        for (int ks = 0; ks < 2; ks++) {
            const uint32_t kso = (uint32_t)(32 * ks);
            uint32_t ah_[4][4], al_[4][4], bb[4][4];
#pragma unroll
            for (int f = 0; f < 4; f++) {
                uint32_t ro = (uint32_t)((wm * 64 + 16 * f) * 80);
                ldsm_x4(ah_[f], sb + TA_H + ro + aoff + kso);
                ldsm_x4(al_[f], sb + TA_L + ro + aoff + kso);
            }
#pragma unroll
            for (int j = 0; j < 4; j++) {
                uint32_t ro = (uint32_t)((wn * 64 + 16 * j) * 80);
                ldsm_x4(bb[j], sb + TB_H + ro + boff + kso);
            }
            // hi*hi : 32 independent accumulators before any reuse
#pragma unroll
            for (int f = 0; f < 4; f++)
#pragma unroll
                for (int j = 0; j < 4; j++) {
                    mma_bf16(acc[f][2 * j + 0], ah_[f], bb[j][0], bb[j][1]);
                    mma_bf16(acc[f][2 * j + 1], ah_[f], bb[j][2], bb[j][3]);
                }
            // lo*hi
#pragma unroll
            for (int f = 0; f < 4; f++)
#pragma unroll
                for (int j = 0; j < 4; j++) {
                    mma_bf16(acc[f][2 * j + 0], al_[f], bb[j][0], bb[j][1]);
                    mma_bf16(acc[f][2 * j + 1], al_[f], bb[j][2], bb[j][3]);
                }
            // hi*lo
#pragma unroll
            for (int j = 0; j < 4; j++) {
                uint32_t ro = (uint32_t)((wn * 64 + 16 * j) * 80);
                ldsm_x4(bb[j], sb + TB_L + ro + boff + kso);
            }
#pragma unroll
            for (int f = 0; f < 4; f++)
#pragma unroll
                for (int j = 0; j < 4; j++) {
                    mma_bf16(acc[f][2 * j + 0], ah_[f], bb[j][0], bb[j][1]);
                    mma_bf16(acc[f][2 * j + 1], ah_[f], bb[j][2], bb[j][3]);
                }
        }
        st ^= 1;
    }

    const int g = lane >> 2, cq = lane & 3;
    if (Chi) {
#pragma unroll
        for (int f = 0; f < 4; f++)
#pragma unroll
            for (int j = 0; j < 8; j++) {
                int row = m0 + wm * 64 + 16 * f + g;
                int col = n0 + wn * 64 + 8 * j + 2 * cq;
                uint32_t h0, l0, h1, l1;
                split2pack(acc[f][j][0], acc[f][j][1], h0, l0);
                split2pack(acc[f][j][2], acc[f][j][3], h1, l1);
                *reinterpret_cast<uint32_t*>(&Chi[(size_t)row * N + col]) = h0;
                *reinterpret_cast<uint32_t*>(&Clo[(size_t)row * N + col]) = l0;
                *reinterpret_cast<uint32_t*>(&Chi[(size_t)(row + 8) * N + col]) = h1;
                *reinterpret_cast<uint32_t*>(&Clo[(size_t)(row + 8) * N + col]) = l1;
            }
    } else {
#pragma unroll
        for (int f = 0; f < 4; f++)
#pragma unroll
            for (int j = 0; j < 8; j++) {
                int row = m0 + wm * 64 + 16 * f + g;
                int col = n0 + wn * 64 + 8 * j + 2 * cq;
                *reinterpret_cast<float2*>(&C[(size_t)row * N + col]) =
                    make_float2(acc[f][j][0], acc[f][j][1]);
                *reinterpret_cast<float2*>(&C[(size_t)(row + 8) * N + col]) =
                    make_float2(acc[f][j][2], acc[f][j][3]);
            }
    }
}

// ============================================================================
// fp32 -> bf16 hi/lo split
// ============================================================================
__global__ __launch_bounds__(256)
void split_bf16(const float* __restrict__ in, __nv_bfloat16* __restrict__ hi,
                __nv_bfloat16* __restrict__ lo, int n4)
{
    int i = blockIdx.x * blockDim.x + threadIdx.x;
    if (i >= n4) return;
    float4 v = *reinterpret_cast<const float4*>(in + (size_t)i * 4);
    uint32_t h0, l0, h1, l1;
    split2pack(v.x, v.y, h0, l0);
    split2pack(v.z, v.w, h1, l1);
    uint32_t* H = reinterpret_cast<uint32_t*>(hi) + (size_t)i * 2;
    uint32_t* L = reinterpret_cast<uint32_t*>(lo) + (size_t)i * 2;
    H[0] = h0; H[1] = h1; L[0] = l0; L[1] = l1;
}

// ============================================================================
// RoPE fused with bf16 hi/lo split; handles Q (y=0) and K (y=1) in one launch.
// ============================================================================
__global__ void init_invfreq()
{
    int i = threadIdx.x;
    g_invfreq[i] = exp(-(double)i * (9.210340371976184 / 64.0));
}

__global__ __launch_bounds__(256)
void rope_split(const float* __restrict__ Qf, const float* __restrict__ Kf,
                __nv_bfloat16* __restrict__ Qhi, __nv_bfloat16* __restrict__ Qlo,
                __nv_bfloat16* __restrict__ Khi, __nv_bfloat16* __restrict__ Klo)
{
    const float* in = blockIdx.y ? Kf : Qf;
    __nv_bfloat16* hi = blockIdx.y ? Khi : Qhi;
    __nv_bfloat16* lo = blockIdx.y ? Klo : Qlo;

    int idx = blockIdx.x * blockDim.x + threadIdx.x;  // [0, B*S*H*64)
    int i = idx & 63;
    int h = (idx >> 6) & (NHEAD - 1);
    int s = (idx >> 10) & (SEQ - 1);
    int b = idx >> 21;

    double inv = g_invfreq[i];
    float ang = (float)((double)s * inv);
    float c, sn;
    sincosf(ang, &sn, &c);

    size_t base = ((size_t)b * SEQ + s) * DIM + (size_t)h * HDIM;
    float x1 = in[base + i];
    float x2 = in[base + 64 + i];
    float y1 = x1 * c - x2 * sn;
    float y2 = x1 * sn + x2 * c;

    __nv_bfloat16 h1 = __float2bfloat16(y1);
    __nv_bfloat16 h2 = __float2bfloat16(y2);
    hi[base + i]      = h1;
    hi[base + 64 + i] = h2;
    lo[base + i]      = __float2bfloat16(y1 - __bfloat162float(h1));
    lo[base + 64 + i] = __float2bfloat16(y2 - __bfloat162float(h2));
}

// ============================================================================
// Tensor-core causal flash attention, bf16x3, fp32 softmax, register P,
// cp.async pipelined K/V. CTA: 128 q-rows; 256 threads = 8 warps x 16 rows.
// Output written directly as bf16 hi/lo (feeds the Wo GEMM).
// smem: Q hi/lo 128x272B, K hi/lo 64x272B, V hi/lo 64x272B = 139264 B.
// ============================================================================
#define FQ_STR 272
#define FQ_H 0
#define FQ_L (FQ_H + 128 * FQ_STR)     // 34816
#define FK_H (FQ_L + 128 * FQ_STR)     // 69632
#define FK_L (FK_H + 64 * FQ_STR)      // 87040
#define FV_H (FK_L + 64 * FQ_STR)      // 104448
#define FV_L (FV_H + 64 * FQ_STR)      // 121856
#define F_SMEM (FV_L + 64 * FQ_STR)    // 139264

__global__ __launch_bounds__(256, 1)
void flash_mma(const __nv_bfloat16* __restrict__ Qh, const __nv_bfloat16* __restrict__ Ql,
               const __nv_bfloat16* __restrict__ Kh, const __nv_bfloat16* __restrict__ Kl,
               const __nv_bfloat16* __restrict__ Vh, const __nv_bfloat16* __restrict__ Vl,
               __nv_bfloat16* __restrict__ Ohi, __nv_bfloat16* __restrict__ Olo)
{
    extern __shared__ __align__(16) char sm[];
    const uint32_t smb = smem_u32(sm);
    const int qt = (int)gridDim.x - 1 - (int)blockIdx.x;  // big tiles first
    const int h  = blockIdx.y;
    const int b  = blockIdx.z;
    const int tid = threadIdx.x;
    const int wid = tid >> 5, lane = tid & 31;
    const int g = lane >> 2, cq = lane & 3;
    const float scale = 0.08838834764831845f;   // 1/sqrt(128)

    const uint32_t aoffQ = (uint32_t)(((lane & 7) + 8 * ((lane >> 3) & 1)) * FQ_STR
                                      + 16 * (lane >> 4));
    const uint32_t boffK = (uint32_t)(((lane & 7) + 8 * (lane >> 4)) * FQ_STR
                                      + 16 * ((lane >> 3) & 1));
    const uint32_t toffV = (uint32_t)(((lane & 7) + 8 * ((lane >> 3) & 1)) * FQ_STR
                                      + 16 * (lane >> 4));

    const size_t rowbase = (size_t)b * SEQ;
    const size_t coloff = (size_t)h * HDIM;
    const int KT = 2 * qt + 2;

    auto load_kv = [&](int kt, bool isK) {
#pragma unroll
        for (int i = 0; i < 4; i++) {
            int s = tid + i * 256;              // 0..1023
            int r = s >> 4, c = s & 15;
            uint32_t so = (uint32_t)(r * FQ_STR + c * 16);
            size_t ga = (rowbase + kt * 64 + r) * DIM + coloff + c * 8;
            if (isK) {
                CP_ASYNC16(smb + FK_H + so, Kh + ga);
                CP_ASYNC16(smb + FK_L + so, Kl + ga);
            } else {
                CP_ASYNC16(smb + FV_H + so, Vh + ga);
                CP_ASYNC16(smb + FV_L + so, Vl + ga);
            }
        }
    };

    // Prologue: group A = Q + K(0); group B = V(0)
#pragma unroll
    for (int i = 0; i < 8; i++) {
        int s = tid + i * 256;                  // 0..2047
        int r = s >> 4, c = s & 15;
        uint32_t so = (uint32_t)(r * FQ_STR + c * 16);
        size_t ga = (rowbase + qt * 128 + r) * DIM + coloff + c * 8;
        CP_ASYNC16(smb + FQ_H + so, Qh + ga);
        CP_ASYNC16(smb + FQ_L + so, Ql + ga);
    }
    load_kv(0, true);
    CP_COMMIT();
    load_kv(0, false);
    CP_COMMIT();

    float oacc[16][4];
#pragma unroll
    for (int f = 0; f < 16; f++)
#pragma unroll
        for (int v = 0; v < 4; v++) oacc[f][v] = 0.f;
    float m0 = -1e30f, m1 = -1e30f, l0 = 0.f, l1 = 0.f;

    for (int kt = 0; kt < KT; kt++) {
        const int ktn = (kt + 1 < KT) ? kt + 1 : kt;

        CP_WAIT1();            // K(kt) (and Q at kt=0) landed
        __syncthreads();

        // ---- S = Q K^T (bf16x3) ----
        float sacc[8][4];
#pragma unroll
        for (int j = 0; j < 8; j++)
#pragma unroll
            for (int v = 0; v < 4; v++) sacc[j][v] = 0.f;

        const uint32_t qrow = (uint32_t)(wid * 16 * FQ_STR);
#pragma unroll
        for (int ks = 0; ks < 8; ks++) {
            const uint32_t kso = (uint32_t)(32 * ks);
            uint32_t ah_[4], al_[4], bh_[4][4];
            ldsm_x4(ah_, smb + FQ_H + qrow + aoffQ + kso);
            ldsm_x4(al_, smb + FQ_L + qrow + aoffQ + kso);
#pragma unroll
            for (int J = 0; J < 4; J++)
                ldsm_x4(bh_[J], smb + FK_H + (uint32_t)(J * 16 * FQ_STR) + boffK + kso);
#pragma unroll
            for (int J = 0; J < 4; J++) {
                mma_bf16(sacc[2 * J + 0], ah_, bh_[J][0], bh_[J][1]);
                mma_bf16(sacc[2 * J + 1], ah_, bh_[J][2], bh_[J][3]);
            }
#pragma unroll
            for (int J = 0; J < 4; J++) {
                mma_bf16(sacc[2 * J + 0], al_, bh_[J][0], bh_[J][1]);
                mma_bf16(sacc[2 * J + 1], al_, bh_[J][2], bh_[J][3]);
            }
#pragma unroll
            for (int J = 0; J < 4; J++) {
                uint32_t bl_[4];
                ldsm_x4(bl_, smb + FK_L + (uint32_t)(J * 16 * FQ_STR) + boffK + kso);
                mma_bf16(sacc[2 * J + 0], ah_, bl_[0], bl_[1]);
                mma_bf16(sacc[2 * J + 1], ah_, bl_[2], bl_[3]);
            }
        }
        __syncthreads();       // all warps done with K smem
        load_kv(ktn, true);    // prefetch K(kt+1) during softmax+PV
        CP_COMMIT();

        // ---- scale + causal mask ----
        const int row0 = qt * 128 + wid * 16 + g;
        const int row1 = row0 + 8;
        const bool diag = (kt >= 2 * qt);
#pragma unroll
        for (int j = 0; j < 8; j++) {
            int colb = kt * 64 + 8 * j + 2 * cq;
#pragma unroll
            for (int v = 0; v < 4; v++) sacc[j][v] *= scale;
            if (diag) {
                if (colb     > row0) sacc[j][0] = -1e30f;
                if (colb + 1 > row0) sacc[j][1] = -1e30f;
                if (colb     > row1) sacc[j][2] = -1e30f;
                if (colb + 1 > row1) sacc[j][3] = -1e30f;
            }
        }

        // ---- online softmax + register-resident P fragments ----
        float mt0 = -1e30f, mt1 = -1e30f;
#pragma unroll
        for (int j = 0; j < 8; j++) {
            mt0 = fmaxf(mt0, fmaxf(sacc[j][0], sacc[j][1]));
            mt1 = fmaxf(mt1, fmaxf(sacc[j][2], sacc[j][3]));
        }
        mt0 = fmaxf(mt0, __shfl_xor_sync(0xffffffffu, mt0, 1));
        mt0 = fmaxf(mt0, __shfl_xor_sync(0xffffffffu, mt0, 2));
        mt1 = fmaxf(mt1, __shfl_xor_sync(0xffffffffu, mt1, 1));
        mt1 = fmaxf(mt1, __shfl_xor_sync(0xffffffffu, mt1, 2));

        float mn0 = fmaxf(m0, mt0), mn1 = fmaxf(m1, mt1);
        float a0 = __expf(m0 - mn0), a1 = __expf(m1 - mn1);
        m0 = mn0; m1 = mn1;

        uint32_t ph0[8], ph1[8], pl0[8], pl1[8];
        float ls0 = 0.f, ls1 = 0.f;
#pragma unroll
        for (int j = 0; j < 8; j++) {
            float p0 = __expf(sacc[j][0] - mn0);
            float p1 = __expf(sacc[j][1] - mn0);
            float p2 = __expf(sacc[j][2] - mn1);
            float p3 = __expf(sacc[j][3] - mn1);
            ls0 += p0 + p1; ls1 += p2 + p3;
            split2pack(p0, p1, ph0[j], pl0[j]);
            split2pack(p2, p3, ph1[j], pl1[j]);
        }
        ls0 += __shfl_xor_sync(0xffffffffu, ls0, 1);
        ls0 += __shfl_xor_sync(0xffffffffu, ls0, 2);
        ls1 += __shfl_xor_sync(0xffffffffu, ls1, 1);
        ls1 += __shfl_xor_sync(0xffffffffu, ls1, 2);
        l0 = l0 * a0 + ls0;
        l1 = l1 * a1 + ls1;
#pragma unroll
        for (int f = 0; f < 16; f++) {
            oacc[f][0] *= a0; oacc[f][1] *= a0;
            oacc[f][2] *= a1; oacc[f][3] *= a1;
        }

        CP_WAIT1();            // V(kt) landed
        __syncthreads();

        // ---- O += P V (bf16x3, register P) ----
#pragma unroll
        for (int ks = 0; ks < 4; ks++) {
            uint32_t a_h[4] = {ph0[2 * ks], ph1[2 * ks], ph0[2 * ks + 1], ph1[2 * ks + 1]};
            uint32_t a_l[4] = {pl0[2 * ks], pl1[2 * ks], pl0[2 * ks + 1], pl1[2 * ks + 1]};
            const uint32_t vrow = (uint32_t)(ks * 16 * FQ_STR);
            uint32_t vv[8][4];
#pragma unroll
            for (int J = 0; J < 8; J++)
                ldsm_x4_t(vv[J], smb + FV_H + vrow + (uint32_t)(J * 32) + toffV);
#pragma unroll
            for (int J = 0; J < 8; J++) {
                mma_bf16(oacc[2 * J + 0], a_h, vv[J][0], vv[J][1]);
                mma_bf16(oacc[2 * J + 1], a_h, vv[J][2], vv[J][3]);
            }
#pragma unroll
            for (int J = 0; J < 8; J++) {
                mma_bf16(oacc[2 * J + 0], a_l, vv[J][0], vv[J][1]);
                mma_bf16(oacc[2 * J + 1], a_l, vv[J][2], vv[J][3]);
            }
#pragma unroll
            for (int J = 0; J < 8; J++)
                ldsm_x4_t(vv[J], smb + FV_L + vrow + (uint32_t)(J * 32) + toffV);
#pragma unroll
            for (int J = 0; J < 8; J++) {
                mma_bf16(oacc[2 * J + 0], a_h, vv[J][0], vv[J][1]);
                mma_bf16(oacc[2 * J + 1], a_h, vv[J][2], vv[J][3]);
            }
        }
        __syncthreads();       // all warps done with V smem
        load_kv(ktn, false);   // prefetch V(kt+1) during next QK
        CP_COMMIT();
    }
    CP_WAIT0();

    // ---- normalize + write O as bf16 hi/lo ----
    const float inv0 = 1.f / l0, inv1 = 1.f / l1;
    const int r0g = qt * 128 + wid * 16 + g;
#pragma unroll
    for (int f = 0; f < 16; f++) {
        int col = 8 * f + 2 * cq;
        size_t b0a = (rowbase + r0g) * DIM + coloff + col;
        size_t b1a = (rowbase + r0g + 8) * DIM + coloff + col;
        uint32_t h0, lo0, h1, lo1;
        split2pack(oacc[f][0] * inv0, oacc[f][1] * inv0, h0, lo0);
        split2pack(oacc[f][2] * inv1, oacc[f][3] * inv1, h1, lo1);
        *reinterpret_cast<uint32_t*>(&Ohi[b0a]) = h0;
        *reinterpret_cast<uint32_t*>(&Olo[b0a]) = lo0;
        *reinterpret_cast<uint32_t*>(&Ohi[b1a]) = h1;
        *reinterpret_cast<uint32_t*>(&Olo[b1a]) = lo1;
    }
}

// ============================================================================
// Launch
// ============================================================================
extern "C" void kernel_launch(void* const* d_in, const int* in_sizes, int n_in,
                              void* d_out, int out_size)
{
    (void)in_sizes; (void)n_in; (void)out_size;
    const float* x  = (const float*)d_in[0];
    const float* Wq = (const float*)d_in[1];
    const float* Wk = (const float*)d_in[2];
    const float* Wv = (const float*)d_in[3];
    const float* Wo = (const float*)d_in[4];
    float* out = (float*)d_out;

    float *Qp, *Kp;
    __nv_bfloat16 *ah, *al, *bh, *bl, *qh, *ql, *kh, *kl, *vh, *vl;
    cudaGetSymbolAddress((void**)&Qp, g_Q);
    cudaGetSymbolAddress((void**)&Kp, g_K);
    cudaGetSymbolAddress((void**)&ah, g_ah);
    cudaGetSymbolAddress((void**)&al, g_al);
    cudaGetSymbolAddress((void**)&bh, g_bh);
    cudaGetSymbolAddress((void**)&bl, g_bl);
    cudaGetSymbolAddress((void**)&qh, g_qh);
    cudaGetSymbolAddress((void**)&ql, g_ql);
    cudaGetSymbolAddress((void**)&kh, g_kh);
    cudaGetSymbolAddress((void**)&kl, g_kl);
    cudaGetSymbolAddress((void**)&vh, g_vh);
    cudaGetSymbolAddress((void**)&vl, g_vl);

    cudaFuncSetAttribute(gemm_mma, cudaFuncAttributeMaxDynamicSharedMemorySize,
                         G_SMEM);
    cudaFuncSetAttribute(flash_mma, cudaFuncAttributeMaxDynamicSharedMemorySize,
                         F_SMEM);

    const dim3 ggrid(DIM / 128, MTOT / 128);   // (16, 32)
    const int nx4 = (int)(ELEMS / 4);
    const int nw4 = (int)(((size_t)DIM * DIM) / 4);

    init_invfreq<<<1, 64>>>();

    // QKV projections (V emits bf16 hi/lo directly)
    split_bf16<<<(nx4 + 255) / 256, 256>>>(x, ah, al, nx4);
    split_bf16<<<(nw4 + 255) / 256, 256>>>(Wq, bh, bl, nw4);
    gemm_mma<<<ggrid, 128, G_SMEM>>>(ah, al, bh, bl, Qp, nullptr, nullptr,
                                     MTOT, DIM, DIM);
    split_bf16<<<(nw4 + 255) / 256, 256>>>(Wk, bh, bl, nw4);
    gemm_mma<<<ggrid, 128, G_SMEM>>>(ah, al, bh, bl, Kp, nullptr, nullptr,
                                     MTOT, DIM, DIM);
    split_bf16<<<(nw4 + 255) / 256, 256>>>(Wv, bh, bl, nw4);
    gemm_mma<<<ggrid, 128, G_SMEM>>>(ah, al, bh, bl, nullptr, vh, vl,
                                     MTOT, DIM, DIM);

    // RoPE + split for Q and K in one launch
    int rope_blocks = (BATCH * SEQ * NHEAD * 64) / 256;   // 16384
    rope_split<<<dim3(rope_blocks, 2), 256>>>(Qp, Kp, qh, ql, kh, kl);

    // Tensor-core causal flash attention -> writes ah/al (bf16 hi/lo)
    flash_mma<<<dim3(SEQ / 128, NHEAD, BATCH), 256, F_SMEM>>>(qh, ql, kh, kl,
                                                              vh, vl, ah, al);

    // Output projection
    split_bf16<<<(nw4 + 255) / 256, 256>>>(Wo, bh, bl, nw4);
    gemm_mma<<<ggrid, 128, G_SMEM>>>(ah, al, bh, bl, out, nullptr, nullptr,
                                     MTOT, DIM, DIM);
}

// round 14
// speedup vs baseline: 3.4124x; 1.0527x over previous
#include <cuda_runtime.h>
#include <cuda_bf16.h>
#include <math.h>
#include <stdint.h>

// Problem constants
#define BATCH 2
#define SEQ   2048
#define DIM   2048
#define NHEAD 16
#define HDIM  128
#define MTOT  (BATCH * SEQ)      // 4096 rows
#define ELEMS ((size_t)BATCH * SEQ * DIM)   // 8388608
#define WSZ   ((size_t)DIM * DIM)           // 4194304

// ---------------- scratch (no allocations allowed) ----------------
__device__ float g_Q[ELEMS];
__device__ float g_K[ELEMS];
__device__ __align__(16) __nv_bfloat16 g_ah[ELEMS];          // A hi (x, then attn-out)
__device__ __align__(16) __nv_bfloat16 g_al[ELEMS];          // A lo
__device__ __align__(16) __nv_bfloat16 g_bh[4 * WSZ];        // Wq,Wk,Wv,Wo hi
__device__ __align__(16) __nv_bfloat16 g_bl[4 * WSZ];        // Wq,Wk,Wv,Wo lo
__device__ __align__(16) __nv_bfloat16 g_qh[ELEMS];
__device__ __align__(16) __nv_bfloat16 g_ql[ELEMS];
__device__ __align__(16) __nv_bfloat16 g_kh[ELEMS];
__device__ __align__(16) __nv_bfloat16 g_kl[ELEMS];
__device__ __align__(16) __nv_bfloat16 g_vh[ELEMS];
__device__ __align__(16) __nv_bfloat16 g_vl[ELEMS];
__device__ double g_invfreq[64];

// ============================================================================
// mma.sync / ldmatrix / cp.async helpers (all legal at compute_103)
// ============================================================================
__device__ __forceinline__ uint32_t smem_u32(const void* p) {
    uint32_t a;
    asm("{ .reg .u64 t; cvta.to.shared.u64 t, %1; cvt.u32.u64 %0, t; }"
        : "=r"(a) : "l"(p));
    return a;
}

__device__ __forceinline__ void ldsm_x4(uint32_t (&r)[4], uint32_t addr) {
    asm volatile("ldmatrix.sync.aligned.m8n8.x4.shared.b16 {%0,%1,%2,%3}, [%4];"
                 : "=r"(r[0]), "=r"(r[1]), "=r"(r[2]), "=r"(r[3]) : "r"(addr));
}

__device__ __forceinline__ void ldsm_x4_t(uint32_t (&r)[4], uint32_t addr) {
    asm volatile("ldmatrix.sync.aligned.m8n8.x4.trans.shared.b16 {%0,%1,%2,%3}, [%4];"
                 : "=r"(r[0]), "=r"(r[1]), "=r"(r[2]), "=r"(r[3]) : "r"(addr));
}

__device__ __forceinline__ void mma_bf16(float (&c)[4], const uint32_t (&a)[4],
                                         uint32_t b0, uint32_t b1) {
    asm volatile(
        "mma.sync.aligned.m16n8k16.row.col.f32.bf16.bf16.f32 "
        "{%0,%1,%2,%3}, {%4,%5,%6,%7}, {%8,%9}, {%0,%1,%2,%3};"
        : "+f"(c[0]), "+f"(c[1]), "+f"(c[2]), "+f"(c[3])
        : "r"(a[0]), "r"(a[1]), "r"(a[2]), "r"(a[3]), "r"(b0), "r"(b1));
}

#define CP_ASYNC16(dst, src) \
    asm volatile("cp.async.ca.shared.global [%0], [%1], 16;" \
                 :: "r"(dst), "l"(src) : "memory")
#define CP_COMMIT() asm volatile("cp.async.commit_group;" ::: "memory")
#define CP_WAIT0()  asm volatile("cp.async.wait_group 0;" ::: "memory")
#define CP_WAIT1()  asm volatile("cp.async.wait_group 1;" ::: "memory")

// hi/lo bf16 pair packing
__device__ __forceinline__ void split2pack(float a, float b, uint32_t& h, uint32_t& l) {
    __nv_bfloat16 ha = __float2bfloat16(a), hb = __float2bfloat16(b);
    __nv_bfloat162 th(ha, hb);
    h = *reinterpret_cast<uint32_t*>(&th);
    __nv_bfloat162 tl(__float2bfloat16(a - __bfloat162float(ha)),
                      __float2bfloat16(b - __bfloat162float(hb)));
    l = *reinterpret_cast<uint32_t*>(&tl);
}

// ============================================================================
// bf16x3 tensor-core GEMM (NT): C[m,n] = sum_k A[m,k]*B[n,k]
// CTA tile 128x128, BK=32, 128 threads = 4 warps (2m x 2n), warp tile 64x64.
// blockIdx.z selects weight slice z and output destination:
//   z=0 -> fp32 C0, z=1 -> fp32 C1, z=2 -> bf16 hi/lo C2h/C2l.
// Inner loop: ALL 16 fragment ldsm hoisted before an uninterrupted 48-mma
// burst per k16-step. 2 CTAs/SM. Double-buffered cp.async.
// ============================================================================
#define G_TILE_B (128 * 80)               // 10240 B per tile
#define TA_H 0
#define TA_L (G_TILE_B)
#define TB_H (2 * G_TILE_B)
#define TB_L (3 * G_TILE_B)
#define G_STAGE (4 * G_TILE_B)            // 40960 per stage
#define G_SMEM (2 * G_STAGE)              // 81920

__global__ __launch_bounds__(128, 2)
void gemm_mma(const __nv_bfloat16* __restrict__ Ah, const __nv_bfloat16* __restrict__ Al,
              const __nv_bfloat16* __restrict__ BhBase,
              const __nv_bfloat16* __restrict__ BlBase,
              float* __restrict__ C0, float* __restrict__ C1,
              __nv_bfloat16* __restrict__ C2h, __nv_bfloat16* __restrict__ C2l,
              int M, int N, int K)
{
    extern __shared__ __align__(16) char sm[];
    const uint32_t smb = smem_u32(sm);
    const int tid = threadIdx.x;
    const int wid = tid >> 5, lane = tid & 31;
    const int wm = wid & 1, wn = wid >> 1;            // 2 x 2 warp grid
    const int m0 = blockIdx.y * 128, n0 = blockIdx.x * 128;
    const int z = blockIdx.z;
    const __nv_bfloat16* Bh = BhBase + (size_t)z * WSZ;
    const __nv_bfloat16* Bl = BlBase + (size_t)z * WSZ;

    const uint32_t aoff = (uint32_t)(((lane & 7) + 8 * ((lane >> 3) & 1)) * 80
                                     + 16 * (lane >> 4));
    const uint32_t boff = (uint32_t)(((lane & 7) + 8 * (lane >> 4)) * 80
                                     + 16 * ((lane >> 3) & 1));

    const int lr = tid >> 2, lc = tid & 3;

    auto load_tiles = [&](int kb, int st) {
        uint32_t base = smb + (uint32_t)(st * G_STAGE);
#pragma unroll
        for (int i = 0; i < 4; i++) {
            int r = lr + 32 * i;
            uint32_t so = (uint32_t)(r * 80 + lc * 16);
            size_t ga = (size_t)(m0 + r) * K + (size_t)kb * 32 + lc * 8;
            size_t gb = (size_t)(n0 + r) * K + (size_t)kb * 32 + lc * 8;
            CP_ASYNC16(base + TA_H + so, Ah + ga);
            CP_ASYNC16(base + TA_L + so, Al + ga);
            CP_ASYNC16(base + TB_H + so, Bh + gb);
            CP_ASYNC16(base + TB_L + so, Bl + gb);
        }
        CP_COMMIT();
    };

    float acc[4][8][4];
#pragma unroll
    for (int i = 0; i < 4; i++)
#pragma unroll
        for (int j = 0; j < 8; j++)
#pragma unroll
            for (int v = 0; v < 4; v++) acc[i][j][v] = 0.f;

    const int KB = K >> 5;
    load_tiles(0, 0);
    int st = 0;
    for (int kb = 0; kb < KB; kb++) {
        CP_WAIT0();
        __syncthreads();
        if (kb + 1 < KB) load_tiles(kb + 1, st ^ 1);

        const uint32_t sb = smb + (uint32_t)(st * G_STAGE);
#pragma unroll
        for (int ks = 0; ks < 2; ks++) {
            const uint32_t kso = (uint32_t)(32 * ks);
            uint32_t ah_[4][4], al_[4][4], bhf[4][4], blf[4][4];
            // hoist ALL fragment loads (16 ldsm) ...
#pragma unroll
            for (int f = 0; f < 4; f++) {
                uint32_t ro = (uint32_t)((wm * 64 + 16 * f) * 80);
                ldsm_x4(ah_[f], sb + TA_H + ro + aoff + kso);
                ldsm_x4(al_[f], sb + TA_L + ro + aoff + kso);
            }
#pragma unroll
            for (int j = 0; j < 4; j++) {
                uint32_t ro = (uint32_t)((wn * 64 + 16 * j) * 80);
                ldsm_x4(bhf[j], sb + TB_H + ro + boff + kso);
                ldsm_x4(blf[j], sb + TB_L + ro + boff + kso);
            }
            // ... then one uninterrupted 48-mma burst (32 indep accumulators)
#pragma unroll
            for (int f = 0; f < 4; f++)
#pragma unroll
                for (int j = 0; j < 4; j++) {
                    mma_bf16(acc[f][2 * j + 0], ah_[f], bhf[j][0], bhf[j][1]);
                    mma_bf16(acc[f][2 * j + 1], ah_[f], bhf[j][2], bhf[j][3]);
                }
#pragma unroll
            for (int f = 0; f < 4; f++)
#pragma unroll
                for (int j = 0; j < 4; j++) {
                    mma_bf16(acc[f][2 * j + 0], al_[f], bhf[j][0], bhf[j][1]);
                    mma_bf16(acc[f][2 * j + 1], al_[f], bhf[j][2], bhf[j][3]);
                }
#pragma unroll
            for (int f = 0; f < 4; f++)
#pragma unroll
                for (int j = 0; j < 4; j++) {
                    mma_bf16(acc[f][2 * j + 0], ah_[f], blf[j][0], blf[j][1]);
                    mma_bf16(acc[f][2 * j + 1], ah_[f], blf[j][2], blf[j][3]);
                }
        }
        st ^= 1;
    }

    const int g = lane >> 2, cq = lane & 3;
    if (z == 2) {
#pragma unroll
        for (int f = 0; f < 4; f++)
#pragma unroll
            for (int j = 0; j < 8; j++) {
                int row = m0 + wm * 64 + 16 * f + g;
                int col = n0 + wn * 64 + 8 * j + 2 * cq;
                uint32_t h0, l0, h1, l1;
                split2pack(acc[f][j][0], acc[f][j][1], h0, l0);
                split2pack(acc[f][j][2], acc[f][j][3], h1, l1);
                *reinterpret_cast<uint32_t*>(&C2h[(size_t)row * N + col]) = h0;
                *reinterpret_cast<uint32_t*>(&C2l[(size_t)row * N + col]) = l0;
                *reinterpret_cast<uint32_t*>(&C2h[(size_t)(row + 8) * N + col]) = h1;
                *reinterpret_cast<uint32_t*>(&C2l[(size_t)(row + 8) * N + col]) = l1;
            }
    } else {
        float* C = z ? C1 : C0;
#pragma unroll
        for (int f = 0; f < 4; f++)
#pragma unroll
            for (int j = 0; j < 8; j++) {
                int row = m0 + wm * 64 + 16 * f + g;
                int col = n0 + wn * 64 + 8 * j + 2 * cq;
                *reinterpret_cast<float2*>(&C[(size_t)row * N + col]) =
                    make_float2(acc[f][j][0], acc[f][j][1]);
                *reinterpret_cast<float2*>(&C[(size_t)(row + 8) * N + col]) =
                    make_float2(acc[f][j][2], acc[f][j][3]);
            }
    }
}

// ============================================================================
// fp32 -> bf16 hi/lo split (single tensor)
// ============================================================================
__global__ __launch_bounds__(256)
void split_bf16(const float* __restrict__ in, __nv_bfloat16* __restrict__ hi,
                __nv_bfloat16* __restrict__ lo, int n4)
{
    int i = blockIdx.x * blockDim.x + threadIdx.x;
    if (i >= n4) return;
    float4 v = *reinterpret_cast<const float4*>(in + (size_t)i * 4);
    uint32_t h0, l0, h1, l1;
    split2pack(v.x, v.y, h0, l0);
    split2pack(v.z, v.w, h1, l1);
    uint32_t* H = reinterpret_cast<uint32_t*>(hi) + (size_t)i * 2;
    uint32_t* L = reinterpret_cast<uint32_t*>(lo) + (size_t)i * 2;
    H[0] = h0; H[1] = h1; L[0] = l0; L[1] = l1;
}

// ============================================================================
// All-4-weights bf16 hi/lo split in one launch (blockIdx.y = weight index)
// ============================================================================
__global__ __launch_bounds__(256)
void split_w4(const float* __restrict__ W0, const float* __restrict__ W1,
              const float* __restrict__ W2, const float* __restrict__ W3,
              __nv_bfloat16* __restrict__ hiB, __nv_bfloat16* __restrict__ loB)
{
    const int w = blockIdx.y;
    const float* in = (w == 0) ? W0 : (w == 1) ? W1 : (w == 2) ? W2 : W3;
    __nv_bfloat16* hi = hiB + (size_t)w * WSZ;
    __nv_bfloat16* lo = loB + (size_t)w * WSZ;

    int i = blockIdx.x * blockDim.x + threadIdx.x;   // < WSZ/4
    float4 v = *reinterpret_cast<const float4*>(in + (size_t)i * 4);
    uint32_t h0, l0, h1, l1;
    split2pack(v.x, v.y, h0, l0);
    split2pack(v.z, v.w, h1, l1);
    uint32_t* H = reinterpret_cast<uint32_t*>(hi) + (size_t)i * 2;
    uint32_t* L = reinterpret_cast<uint32_t*>(lo) + (size_t)i * 2;
    H[0] = h0; H[1] = h1; L[0] = l0; L[1] = l1;
}

// ============================================================================
// RoPE fused with bf16 hi/lo split; handles Q (y=0) and K (y=1) in one launch.
// ============================================================================
__global__ void init_invfreq()
{
    int i = threadIdx.x;
    g_invfreq[i] = exp(-(double)i * (9.210340371976184 / 64.0));
}

__global__ __launch_bounds__(256)
void rope_split(const float* __restrict__ Qf, const float* __restrict__ Kf,
                __nv_bfloat16* __restrict__ Qhi, __nv_bfloat16* __restrict__ Qlo,
                __nv_bfloat16* __restrict__ Khi, __nv_bfloat16* __restrict__ Klo)
{
    const float* in = blockIdx.y ? Kf : Qf;
    __nv_bfloat16* hi = blockIdx.y ? Khi : Qhi;
    __nv_bfloat16* lo = blockIdx.y ? Klo : Qlo;

    int idx = blockIdx.x * blockDim.x + threadIdx.x;  // [0, B*S*H*64)
    int i = idx & 63;
    int h = (idx >> 6) & (NHEAD - 1);
    int s = (idx >> 10) & (SEQ - 1);
    int b = idx >> 21;

    double inv = g_invfreq[i];
    float ang = (float)((double)s * inv);
    float c, sn;
    sincosf(ang, &sn, &c);

    size_t base = ((size_t)b * SEQ + s) * DIM + (size_t)h * HDIM;
    float x1 = in[base + i];
    float x2 = in[base + 64 + i];
    float y1 = x1 * c - x2 * sn;
    float y2 = x1 * sn + x2 * c;

    __nv_bfloat16 h1 = __float2bfloat16(y1);
    __nv_bfloat16 h2 = __float2bfloat16(y2);
    hi[base + i]      = h1;
    hi[base + 64 + i] = h2;
    lo[base + i]      = __float2bfloat16(y1 - __bfloat162float(h1));
    lo[base + 64 + i] = __float2bfloat16(y2 - __bfloat162float(h2));
}

// ============================================================================
// Tensor-core causal flash attention, bf16x3, fp32 softmax, register P,
// cp.async pipelined K/V. CTA: 128 q-rows; 256 threads = 8 warps x 16 rows.
// Output written directly as bf16 hi/lo (feeds the Wo GEMM).
// ============================================================================
#define FQ_STR 272
#define FQ_H 0
#define FQ_L (FQ_H + 128 * FQ_STR)     // 34816
#define FK_H (FQ_L + 128 * FQ_STR)     // 69632
#define FK_L (FK_H + 64 * FQ_STR)      // 87040
#define FV_H (FK_L + 64 * FQ_STR)      // 104448
#define FV_L (FV_H + 64 * FQ_STR)      // 121856
#define F_SMEM (FV_L + 64 * FQ_STR)    // 139264

__global__ __launch_bounds__(256, 1)
void flash_mma(const __nv_bfloat16* __restrict__ Qh, const __nv_bfloat16* __restrict__ Ql,
               const __nv_bfloat16* __restrict__ Kh, const __nv_bfloat16* __restrict__ Kl,
               const __nv_bfloat16* __restrict__ Vh, const __nv_bfloat16* __restrict__ Vl,
               __nv_bfloat16* __restrict__ Ohi, __nv_bfloat16* __restrict__ Olo)
{
    extern __shared__ __align__(16) char sm[];
    const uint32_t smb = smem_u32(sm);
    const int qt = (int)gridDim.x - 1 - (int)blockIdx.x;  // big tiles first
    const int h  = blockIdx.y;
    const int b  = blockIdx.z;
    const int tid = threadIdx.x;
    const int wid = tid >> 5, lane = tid & 31;
    const int g = lane >> 2, cq = lane & 3;
    const float scale = 0.08838834764831845f;   // 1/sqrt(128)

    const uint32_t aoffQ = (uint32_t)(((lane & 7) + 8 * ((lane >> 3) & 1)) * FQ_STR
                                      + 16 * (lane >> 4));
    const uint32_t boffK = (uint32_t)(((lane & 7) + 8 * (lane >> 4)) * FQ_STR
                                      + 16 * ((lane >> 3) & 1));
    const uint32_t toffV = (uint32_t)(((lane & 7) + 8 * ((lane >> 3) & 1)) * FQ_STR
                                      + 16 * (lane >> 4));

    const size_t rowbase = (size_t)b * SEQ;
    const size_t coloff = (size_t)h * HDIM;
    const int KT = 2 * qt + 2;

    auto load_kv = [&](int kt, bool isK) {
#pragma unroll
        for (int i = 0; i < 4; i++) {
            int s = tid + i * 256;              // 0..1023
            int r = s >> 4, c = s & 15;
            uint32_t so = (uint32_t)(r * FQ_STR + c * 16);
            size_t ga = (rowbase + kt * 64 + r) * DIM + coloff + c * 8;
            if (isK) {
                CP_ASYNC16(smb + FK_H + so, Kh + ga);
                CP_ASYNC16(smb + FK_L + so, Kl + ga);
            } else {
                CP_ASYNC16(smb + FV_H + so, Vh + ga);
                CP_ASYNC16(smb + FV_L + so, Vl + ga);
            }
        }
    };

    // Prologue: group A = Q + K(0); group B = V(0)
#pragma unroll
    for (int i = 0; i < 8; i++) {
        int s = tid + i * 256;                  // 0..2047
        int r = s >> 4, c = s & 15;
        uint32_t so = (uint32_t)(r * FQ_STR + c * 16);
        size_t ga = (rowbase + qt * 128 + r) * DIM + coloff + c * 8;
        CP_ASYNC16(smb + FQ_H + so, Qh + ga);
        CP_ASYNC16(smb + FQ_L + so, Ql + ga);
    }
    load_kv(0, true);
    CP_COMMIT();
    load_kv(0, false);
    CP_COMMIT();

    float oacc[16][4];
#pragma unroll
    for (int f = 0; f < 16; f++)
#pragma unroll
        for (int v = 0; v < 4; v++) oacc[f][v] = 0.f;
    float m0 = -1e30f, m1 = -1e30f, l0 = 0.f, l1 = 0.f;

    for (int kt = 0; kt < KT; kt++) {
        const int ktn = (kt + 1 < KT) ? kt + 1 : kt;

        CP_WAIT1();            // K(kt) (and Q at kt=0) landed
        __syncthreads();

        // ---- S = Q K^T (bf16x3) ----
        float sacc[8][4];
#pragma unroll
        for (int j = 0; j < 8; j++)
#pragma unroll
            for (int v = 0; v < 4; v++) sacc[j][v] = 0.f;

        const uint32_t qrow = (uint32_t)(wid * 16 * FQ_STR);
#pragma unroll
        for (int ks = 0; ks < 8; ks++) {
            const uint32_t kso = (uint32_t)(32 * ks);
            uint32_t ah_[4], al_[4], bh_[4][4];
            ldsm_x4(ah_, smb + FQ_H + qrow + aoffQ + kso);
            ldsm_x4(al_, smb + FQ_L + qrow + aoffQ + kso);
#pragma unroll
            for (int J = 0; J < 4; J++)
                ldsm_x4(bh_[J], smb + FK_H + (uint32_t)(J * 16 * FQ_STR) + boffK + kso);
#pragma unroll
            for (int J = 0; J < 4; J++) {
                mma_bf16(sacc[2 * J + 0], ah_, bh_[J][0], bh_[J][1]);
                mma_bf16(sacc[2 * J + 1], ah_, bh_[J][2], bh_[J][3]);
            }
#pragma unroll
            for (int J = 0; J < 4; J++) {
                mma_bf16(sacc[2 * J + 0], al_, bh_[J][0], bh_[J][1]);
                mma_bf16(sacc[2 * J + 1], al_, bh_[J][2], bh_[J][3]);
            }
#pragma unroll
            for (int J = 0; J < 4; J++) {
                uint32_t bl_[4];
                ldsm_x4(bl_, smb + FK_L + (uint32_t)(J * 16 * FQ_STR) + boffK + kso);
                mma_bf16(sacc[2 * J + 0], ah_, bl_[0], bl_[1]);
                mma_bf16(sacc[2 * J + 1], ah_, bl_[2], bl_[3]);
            }
        }
        __syncthreads();       // all warps done with K smem
        load_kv(ktn, true);    // prefetch K(kt+1) during softmax+PV
        CP_COMMIT();

        // ---- scale + causal mask ----
        const int row0 = qt * 128 + wid * 16 + g;
        const int row1 = row0 + 8;
        const bool diag = (kt >= 2 * qt);
#pragma unroll
        for (int j = 0; j < 8; j++) {
            int colb = kt * 64 + 8 * j + 2 * cq;
#pragma unroll
            for (int v = 0; v < 4; v++) sacc[j][v] *= scale;
            if (diag) {
                if (colb     > row0) sacc[j][0] = -1e30f;
                if (colb + 1 > row0) sacc[j][1] = -1e30f;
                if (colb     > row1) sacc[j][2] = -1e30f;
                if (colb + 1 > row1) sacc[j][3] = -1e30f;
            }
        }

        // ---- online softmax + register-resident P fragments ----
        float mt0 = -1e30f, mt1 = -1e30f;
#pragma unroll
        for (int j = 0; j < 8; j++) {
            mt0 = fmaxf(mt0, fmaxf(sacc[j][0], sacc[j][1]));
            mt1 = fmaxf(mt1, fmaxf(sacc[j][2], sacc[j][3]));
        }
        mt0 = fmaxf(mt0, __shfl_xor_sync(0xffffffffu, mt0, 1));
        mt0 = fmaxf(mt0, __shfl_xor_sync(0xffffffffu, mt0, 2));
        mt1 = fmaxf(mt1, __shfl_xor_sync(0xffffffffu, mt1, 1));
        mt1 = fmaxf(mt1, __shfl_xor_sync(0xffffffffu, mt1, 2));

        float mn0 = fmaxf(m0, mt0), mn1 = fmaxf(m1, mt1);
        float a0 = __expf(m0 - mn0), a1 = __expf(m1 - mn1);
        m0 = mn0; m1 = mn1;

        uint32_t ph0[8], ph1[8], pl0[8], pl1[8];
        float ls0 = 0.f, ls1 = 0.f;
#pragma unroll
        for (int j = 0; j < 8; j++) {
            float p0 = __expf(sacc[j][0] - mn0);
            float p1 = __expf(sacc[j][1] - mn0);
            float p2 = __expf(sacc[j][2] - mn1);
            float p3 = __expf(sacc[j][3] - mn1);
            ls0 += p0 + p1; ls1 += p2 + p3;
            split2pack(p0, p1, ph0[j], pl0[j]);
            split2pack(p2, p3, ph1[j], pl1[j]);
        }
        ls0 += __shfl_xor_sync(0xffffffffu, ls0, 1);
        ls0 += __shfl_xor_sync(0xffffffffu, ls0, 2);
        ls1 += __shfl_xor_sync(0xffffffffu, ls1, 1);
        ls1 += __shfl_xor_sync(0xffffffffu, ls1, 2);
        l0 = l0 * a0 + ls0;
        l1 = l1 * a1 + ls1;
#pragma unroll
        for (int f = 0; f < 16; f++) {
            oacc[f][0] *= a0; oacc[f][1] *= a0;
            oacc[f][2] *= a1; oacc[f][3] *= a1;
        }

        CP_WAIT1();            // V(kt) landed
        __syncthreads();

        // ---- O += P V (bf16x3, register P) ----
#pragma unroll
        for (int ks = 0; ks < 4; ks++) {
            uint32_t a_h[4] = {ph0[2 * ks], ph1[2 * ks], ph0[2 * ks + 1], ph1[2 * ks + 1]};
            uint32_t a_l[4] = {pl0[2 * ks], pl1[2 * ks], pl0[2 * ks + 1], pl1[2 * ks + 1]};
            const uint32_t vrow = (uint32_t)(ks * 16 * FQ_STR);
            uint32_t vv[8][4];
#pragma unroll
            for (int J = 0; J < 8; J++)
                ldsm_x4_t(vv[J], smb + FV_H + vrow + (uint32_t)(J * 32) + toffV);
#pragma unroll
            for (int J = 0; J < 8; J++) {
                mma_bf16(oacc[2 * J + 0], a_h, vv[J][0], vv[J][1]);
                mma_bf16(oacc[2 * J + 1], a_h, vv[J][2], vv[J][3]);
            }
#pragma unroll
            for (int J = 0; J < 8; J++) {
                mma_bf16(oacc[2 * J + 0], a_l, vv[J][0], vv[J][1]);
                mma_bf16(oacc[2 * J + 1], a_l, vv[J][2], vv[J][3]);
            }
#pragma unroll
            for (int J = 0; J < 8; J++)
                ldsm_x4_t(vv[J], smb + FV_L + vrow + (uint32_t)(J * 32) + toffV);
#pragma unroll
            for (int J = 0; J < 8; J++) {
                mma_bf16(oacc[2 * J + 0], a_h, vv[J][0], vv[J][1]);
                mma_bf16(oacc[2 * J + 1], a_h, vv[J][2], vv[J][3]);
            }
        }
        __syncthreads();       // all warps done with V smem
        load_kv(ktn, false);   // prefetch V(kt+1) during next QK
        CP_COMMIT();
    }
    CP_WAIT0();

    // ---- normalize + write O as bf16 hi/lo ----
    const float inv0 = 1.f / l0, inv1 = 1.f / l1;
    const int r0g = qt * 128 + wid * 16 + g;
#pragma unroll
    for (int f = 0; f < 16; f++) {
        int col = 8 * f + 2 * cq;
        size_t b0a = (rowbase + r0g) * DIM + coloff + col;
        size_t b1a = (rowbase + r0g + 8) * DIM + coloff + col;
        uint32_t h0, lo0, h1, lo1;
        split2pack(oacc[f][0] * inv0, oacc[f][1] * inv0, h0, lo0);
        split2pack(oacc[f][2] * inv1, oacc[f][3] * inv1, h1, lo1);
        *reinterpret_cast<uint32_t*>(&Ohi[b0a]) = h0;
        *reinterpret_cast<uint32_t*>(&Olo[b0a]) = lo0;
        *reinterpret_cast<uint32_t*>(&Ohi[b1a]) = h1;
        *reinterpret_cast<uint32_t*>(&Olo[b1a]) = lo1;
    }
}

// ============================================================================
// Launch
// ============================================================================
extern "C" void kernel_launch(void* const* d_in, const int* in_sizes, int n_in,
                              void* d_out, int out_size)
{
    (void)in_sizes; (void)n_in; (void)out_size;
    const float* x  = (const float*)d_in[0];
    const float* Wq = (const float*)d_in[1];
    const float* Wk = (const float*)d_in[2];
    const float* Wv = (const float*)d_in[3];
    const float* Wo = (const float*)d_in[4];
    float* out = (float*)d_out;

    float *Qp, *Kp;
    __nv_bfloat16 *ah, *al, *bh, *bl, *qh, *ql, *kh, *kl, *vh, *vl;
    cudaGetSymbolAddress((void**)&Qp, g_Q);
    cudaGetSymbolAddress((void**)&Kp, g_K);
    cudaGetSymbolAddress((void**)&ah, g_ah);
    cudaGetSymbolAddress((void**)&al, g_al);
    cudaGetSymbolAddress((void**)&bh, g_bh);
    cudaGetSymbolAddress((void**)&bl, g_bl);
    cudaGetSymbolAddress((void**)&qh, g_qh);
    cudaGetSymbolAddress((void**)&ql, g_ql);
    cudaGetSymbolAddress((void**)&kh, g_kh);
    cudaGetSymbolAddress((void**)&kl, g_kl);
    cudaGetSymbolAddress((void**)&vh, g_vh);
    cudaGetSymbolAddress((void**)&vl, g_vl);

    cudaFuncSetAttribute(gemm_mma, cudaFuncAttributeMaxDynamicSharedMemorySize,
                         G_SMEM);
    cudaFuncSetAttribute(flash_mma, cudaFuncAttributeMaxDynamicSharedMemorySize,
                         F_SMEM);

    const int nx4 = (int)(ELEMS / 4);
    const int nw4 = (int)(WSZ / 4);

    init_invfreq<<<1, 64>>>();

    // All weight splits in one launch; x split
    split_w4<<<dim3(nw4 / 256, 4), 256>>>(Wq, Wk, Wv, Wo, bh, bl);
    split_bf16<<<(nx4 + 255) / 256, 256>>>(x, ah, al, nx4);

    // Fused QKV projection: z=0 -> Q (fp32), z=1 -> K (fp32), z=2 -> V (bf16)
    gemm_mma<<<dim3(DIM / 128, MTOT / 128, 3), 128, G_SMEM>>>(
        ah, al, bh, bl, Qp, Kp, vh, vl, MTOT, DIM, DIM);

    // RoPE + split for Q and K in one launch
    int rope_blocks = (BATCH * SEQ * NHEAD * 64) / 256;   // 16384
    rope_split<<<dim3(rope_blocks, 2), 256>>>(Qp, Kp, qh, ql, kh, kl);

    // Tensor-core causal flash attention -> writes ah/al (bf16 hi/lo)
    flash_mma<<<dim3(SEQ / 128, NHEAD, BATCH), 256, F_SMEM>>>(qh, ql, kh, kl,
                                                              vh, vl, ah, al);

    // Output projection (weight slice 3); z=0 path writes fp32 to out
    gemm_mma<<<dim3(DIM / 128, MTOT / 128, 1), 128, G_SMEM>>>(
        ah, al, bh + 3 * WSZ, bl + 3 * WSZ, out, nullptr, nullptr, nullptr,
        MTOT, DIM, DIM);
}